// round 9
// baseline (speedup 1.0000x reference)
#include <cuda_runtime.h>

#define BATCH 4
#define SEQL  4096
#define DIN   128
#define NST   16
#define TCH   32
#define NCH   128   /* SEQL / TCH */

typedef unsigned long long u64;

#define FMA2(d, a, b, c) asm("fma.rn.f32x2 %0, %1, %2, %3;" : "=l"(d) : "l"(a), "l"(b), "l"(c))
#define MUL2(d, a, b)    asm("mul.rn.f32x2 %0, %1, %2;" : "=l"(d) : "l"(a), "l"(b))
#define UNPK2(x, y, in)  asm("mov.b64 {%0, %1}, %2;" : "=f"(x), "=f"(y) : "l"(in))
#define PK1(d, x)        asm("mov.b64 %0, {%1, %1};" : "=l"(d) : "f"(x))
#define PKP(d, x, y)     asm("mov.b64 %0, {%1, %2};" : "=l"(d) : "f"(x), "f"(y))

#define CPA16(dst, src)  asm volatile("cp.async.cg.shared.global [%0], [%1], 16;" :: "r"(dst), "l"(src) : "memory")
#define CPCOM()          asm volatile("cp.async.commit_group;" ::: "memory")
#define CPWAIT1()        asm volatile("cp.async.wait_group 1;" ::: "memory")
#define CPWAIT0()        asm volatile("cp.async.wait_group 0;" ::: "memory")

// ---------------- scratch (device globals; no allocation) ----------------
__device__ float g_xr  [BATCH*SEQL*256];   // in_proj output (u | res), row-major [l][256]
__device__ float g_u   [BATCH*DIN*SEQL];   // silu(conv(u)), k-major [b][d][l]
__device__ float g_xdbl[BATCH*SEQL*36];    // x_proj output, row-major [l][36] (dt4|B16|C16)
__device__ float g_hp  [BATCH*NCH*DIN*32]; // per-chunk [h_end(16)|P(16)] -> H_init
__device__ float g_yg  [BATCH*DIN*SEQL];   // gated scan output, k-major [b][d][l]
__device__ float g_xmid[BATCH*64*SEQL];    // between mambas, k-major [b][c][l]
__device__ float g_w1t [2][64*256];        // in_proj W transposed [k][n]
__device__ float g_wxt [2][128*64];        // x_proj W transposed, zero-padded to 64
__device__ float g_wot [2][128*64];        // out_proj W transposed
__device__ float g_Ab  [2][DIN*NST];       // A = -exp(Alog)
__device__ int   g_Afl [2];                // 1 if A[d][n] == (n+1)*A[d][0]
__device__ unsigned g_ctr = 0;             // grid-barrier ticket counter (monotonic)

__device__ __forceinline__ float softplusf(float x) {
    return x > 15.f ? x : __logf(1.f + __expf(x));
}
__device__ __forceinline__ float siluf(float x) {
    return x / (1.f + __expf(-x));
}

// ---------------- prep: both mambas in one launch ----------------
__global__ void prep_k(const float* __restrict__ iw0, const float* __restrict__ xp0,
                       const float* __restrict__ ow0, const float* __restrict__ al0,
                       const float* __restrict__ iw1, const float* __restrict__ xp1,
                       const float* __restrict__ ow1, const float* __restrict__ al1,
                       float* __restrict__ w1t, float* __restrict__ wxt,
                       float* __restrict__ wot, float* __restrict__ Ab) {
    int m = blockIdx.y;
    const float* in_w  = m ? iw1 : iw0;
    const float* xproj = m ? xp1 : xp0;
    const float* out_w = m ? ow1 : ow0;
    const float* Alog  = m ? al1 : al0;
    float* w1 = w1t + m*16384;
    float* wx = wxt + m*8192;
    float* wo = wot + m*8192;
    float* Am = Ab  + m*2048;
    int idx = blockIdx.x * 256 + threadIdx.x;
    if (idx < 16384) { int k = idx >> 8, n = idx & 255; w1[idx] = in_w[n*64 + k]; return; }
    idx -= 16384;
    if (idx < 8192)  { int k = idx >> 6, n = idx & 63; wx[idx] = (n < 36) ? xproj[n*128 + k] : 0.f; return; }
    idx -= 8192;
    if (idx < 8192)  { int k = idx >> 6, n = idx & 63; wo[idx] = out_w[n*128 + k]; return; }
    idx -= 8192;
    if (idx < 2048)  Am[idx] = -expf(Alog[idx]);
}

__global__ void chkA_k(const float* __restrict__ A0, const float* __restrict__ A1,
                       int* __restrict__ fl) {
    const float* A = blockIdx.x ? A1 : A0;
    __shared__ int ok;
    if (threadIdx.x == 0) ok = 1;
    __syncthreads();
    int bad = 0;
    for (int e = threadIdx.x; e < DIN*NST; e += 256) {
        int d = e >> 4, n = e & 15;
        float expv = (float)(n + 1) * A[d*16];
        if (fabsf(A[e] - expv) > 1e-5f * fabsf(expv) + 1e-20f) bad = 1;
    }
    if (bad) atomicAnd(&ok, 0);
    __syncthreads();
    if (threadIdx.x == 0) fl[blockIdx.x] = ok;
}

// ---------------- pipelined GEMM: X k-major [b][K][4096]; tile 64L x 64N ----------------
// 2-stage cp.async over k-tiles of 32. 4L x 4N per thread (2 f32x2 row-pairs).
// epi: 0 = row-major [l][Nout] at col n0;
//      2 = LayerNorm over 64 cols + transposed write [b][64][4096].
__global__ __launch_bounds__(256) void gemm_k(
    const float* __restrict__ X, const float* __restrict__ Wt, float* __restrict__ Out,
    int K, int Nld, int Nout, int epi,
    const float* __restrict__ lng, const float* __restrict__ lnb)
{
    extern __shared__ float sm[];  // [2][32*64] X | [2][32*64] W  (epilogue staging reuse)
    int tid = threadIdx.x;
    int l0 = blockIdx.x << 6;
    int n0 = blockIdx.y << 6;
    int b  = blockIdx.z;
    const float* Xb = X + (long)b * K * SEQL;
    int lj = tid >> 4, ng = tid & 15;
    int lb = lj << 2;
    unsigned smb = (unsigned)__cvta_generic_to_shared(sm);
    int ntiles = K >> 5;

    // issue tile 0 into stage 0
    {
#pragma unroll
        for (int i = 0; i < 2; i++) {
            int e = tid + (i << 8);
            int k = e >> 4, lq = e & 15;
            CPA16(smb + (((k << 6) + (lq << 2)) << 2),
                  Xb + (long)k * SEQL + l0 + (lq << 2));
        }
#pragma unroll
        for (int i = 0; i < 2; i++) {
            int e = tid + (i << 8);
            int k = e >> 4, nq = e & 15;
            CPA16(smb + 16384u + (((k << 6) + (nq << 2)) << 2),
                  Wt + (long)k * Nld + n0 + (nq << 2));
        }
        CPCOM();
    }

    u64 acc[2][4];
#pragma unroll
    for (int p = 0; p < 2; p++)
#pragma unroll
        for (int c = 0; c < 4; c++) acc[p][c] = 0ULL;

    for (int tt = 0; tt < ntiles; tt++) {
        int s = tt & 1;
        if (tt + 1 < ntiles) {
            int kofs = (tt + 1) << 5;
            int s2 = s ^ 1;
#pragma unroll
            for (int i = 0; i < 2; i++) {
                int e = tid + (i << 8);
                int k = e >> 4, lq = e & 15;
                CPA16(smb + (((s2 << 11) + (k << 6) + (lq << 2)) << 2),
                      Xb + (long)(kofs + k) * SEQL + l0 + (lq << 2));
            }
#pragma unroll
            for (int i = 0; i < 2; i++) {
                int e = tid + (i << 8);
                int k = e >> 4, nq = e & 15;
                CPA16(smb + 16384u + (((s2 << 11) + (k << 6) + (nq << 2)) << 2),
                      Wt + (long)(kofs + k) * Nld + n0 + (nq << 2));
            }
            CPCOM();
            CPWAIT1();
        } else {
            CPWAIT0();
        }
        __syncthreads();
        const float* xs = sm + (s << 11);
        const float* ws = sm + 4096 + (s << 11);
#pragma unroll 8
        for (int kk = 0; kk < 32; kk++) {
            ulonglong2 av = *(const ulonglong2*)&xs[(kk << 6) + lb];   // rows (0,1),(2,3)
            float4 wv = *(const float4*)&ws[(kk << 6) + (ng << 2)];
            u64 b0, b1, b2, b3;
            PK1(b0, wv.x); PK1(b1, wv.y); PK1(b2, wv.z); PK1(b3, wv.w);
            FMA2(acc[0][0], av.x, b0, acc[0][0]); FMA2(acc[0][1], av.x, b1, acc[0][1]);
            FMA2(acc[0][2], av.x, b2, acc[0][2]); FMA2(acc[0][3], av.x, b3, acc[0][3]);
            FMA2(acc[1][0], av.y, b0, acc[1][0]); FMA2(acc[1][1], av.y, b1, acc[1][1]);
            FMA2(acc[1][2], av.y, b2, acc[1][2]); FMA2(acc[1][3], av.y, b3, acc[1][3]);
        }
        __syncthreads();
    }

    if (epi == 0) {
#pragma unroll
        for (int p = 0; p < 2; p++) {
            float lo[4], hi[4];
#pragma unroll
            for (int c = 0; c < 4; c++) UNPK2(lo[c], hi[c], acc[p][c]);
            long r0 = ((long)b*SEQL + l0 + lb + 2*p) * Nout + n0 + (ng << 2);
            *(float4*)&Out[r0]        = make_float4(lo[0], lo[1], lo[2], lo[3]);
            *(float4*)&Out[r0 + Nout] = make_float4(hi[0], hi[1], hi[2], hi[3]);
        }
    } else {
        // LayerNorm over 64 cols + transposed coalesced write (n0==0)
        float* st  = sm;          // [64 l][65]
        float* st2 = sm + 4160;   // [64 n][65] transposed
#pragma unroll
        for (int p = 0; p < 2; p++) {
#pragma unroll
            for (int c = 0; c < 4; c++) {
                float lo, hi;
                UNPK2(lo, hi, acc[p][c]);
                st[(lb + 2*p)*65 + (ng << 2) + c]     = lo;
                st[(lb + 2*p + 1)*65 + (ng << 2) + c] = hi;
            }
        }
        __syncthreads();
        int row = tid >> 2, q = tid & 3;
        float v[16], s = 0.f, s2 = 0.f;
#pragma unroll
        for (int j = 0; j < 16; j++) {
            float x = st[row*65 + q*16 + j];
            v[j] = x; s += x; s2 += x * x;
        }
        s  += __shfl_xor_sync(0xffffffffu, s, 1);
        s2 += __shfl_xor_sync(0xffffffffu, s2, 1);
        s  += __shfl_xor_sync(0xffffffffu, s, 2);
        s2 += __shfl_xor_sync(0xffffffffu, s2, 2);
        float mean = s * 0.015625f;
        float var  = s2 * 0.015625f - mean * mean;
        float rstd = rsqrtf(var + 1e-5f);
#pragma unroll
        for (int j = 0; j < 16; j++) {
            int n = q*16 + j;
            st2[n*65 + row] = (v[j] - mean) * rstd * __ldg(&lng[n]) + __ldg(&lnb[n]);
        }
        __syncthreads();
        int n2 = tid >> 2, lq = tid & 3;
#pragma unroll
        for (int i = 0; i < 4; i++) {
            int l = (lq << 4) + (i << 2);
            float4 o4 = make_float4(st2[n2*65 + l], st2[n2*65 + l + 1],
                                    st2[n2*65 + l + 2], st2[n2*65 + l + 3]);
            *(float4*)&Out[((long)b*64 + n2)*SEQL + l0 + l] = o4;
        }
    }
}

// ---------------- FUSED conv+silu + x_proj GEMM ----------------
// Block = 64 l x all 128 d. Loads xr halo, computes u into smem, writes u to
// global (k-major), then does the K=128 GEMM -> xd[l][36] straight from smem.
#define US_P 68   /* us tile pitch: 68*4=272B, 16B-aligned */
__global__ __launch_bounds__(256) void cxp_k(const float* __restrict__ xr,
                                             const float* __restrict__ cw,
                                             const float* __restrict__ cb,
                                             const float* __restrict__ wxt,
                                             float* __restrict__ u,
                                             float* __restrict__ xd) {
    extern __shared__ float sm[];
    float* xh = sm;                 // [67 rows][132]  (row = l0-3+row)
    float* ws = sm + 67*132;        // [128 k][64 n]
    float* us = ws + 128*64;        // [128 d][US_P]   (silu(conv(u)))
    int tid = threadIdx.x;
    int l0 = blockIdx.x << 6;
    int b  = blockIdx.y;

    // load halo tile: 67 rows x 128 d, float4 along d
    for (int e = tid; e < 67*32; e += 256) {
        int row = e >> 5, d4 = e & 31;
        int lg = l0 - 3 + row;
        float4 v = (lg >= 0) ? *(const float4*)&xr[((long)b*SEQL + lg)*256 + (d4 << 2)]
                             : make_float4(0.f, 0.f, 0.f, 0.f);
        *(float4*)&xh[row*132 + (d4 << 2)] = v;
    }
    // load W tile [128][64] (wxt already [k][64] contiguous)
    for (int e = tid; e < 2048; e += 256)
        *(float4*)&ws[e << 2] = *(const float4*)&wxt[e << 2];
    __syncthreads();

    // conv + silu: thread = (half = tid>>7, d = tid&127); 32 l each; conflict-free
    {
        int d = tid & 127, half = tid >> 7;
        float4 w = *(const float4*)&cw[d*4];
        float bias = __ldg(&cb[d]);
        int lbase = half << 5;
#pragma unroll
        for (int g = 0; g < 8; g++) {
            float o4[4];
#pragma unroll
            for (int i = 0; i < 4; i++) {
                int l = lbase + (g << 2) + i;   // local l; xh row l..l+3 = l-3..l
                float s = fmaf(w.x, xh[l*132 + d], fmaf(w.y, xh[(l+1)*132 + d],
                          fmaf(w.z, xh[(l+2)*132 + d], fmaf(w.w, xh[(l+3)*132 + d], bias))));
                o4[i] = siluf(s);
            }
            *(float4*)&us[d*US_P + lbase + (g << 2)] =
                make_float4(o4[0], o4[1], o4[2], o4[3]);
        }
    }
    __syncthreads();

    // write u to global, k-major, float4 along l
    for (int e = tid; e < 2048; e += 256) {
        int d2 = e >> 4, l4 = e & 15;
        int lcc = l4 << 2;
        float4 o4 = make_float4(us[d2*US_P + lcc],     us[d2*US_P + lcc + 1],
                                us[d2*US_P + lcc + 2], us[d2*US_P + lcc + 3]);
        *(float4*)&u[((long)b*DIN + d2)*SEQL + l0 + lcc] = o4;
    }

    // GEMM: 64l x 64n (36 useful) x K=128, straight from smem
    int lj = tid >> 4, ng = tid & 15;
    int lb = lj << 2;
    u64 acc[2][4];
#pragma unroll
    for (int p = 0; p < 2; p++)
#pragma unroll
        for (int c = 0; c < 4; c++) acc[p][c] = 0ULL;

#pragma unroll 8
    for (int kk = 0; kk < 128; kk++) {
        ulonglong2 av = *(const ulonglong2*)&us[kk*US_P + lb];
        float4 wv = *(const float4*)&ws[(kk << 6) + (ng << 2)];
        u64 b0, b1, b2, b3;
        PK1(b0, wv.x); PK1(b1, wv.y); PK1(b2, wv.z); PK1(b3, wv.w);
        FMA2(acc[0][0], av.x, b0, acc[0][0]); FMA2(acc[0][1], av.x, b1, acc[0][1]);
        FMA2(acc[0][2], av.x, b2, acc[0][2]); FMA2(acc[0][3], av.x, b3, acc[0][3]);
        FMA2(acc[1][0], av.y, b0, acc[1][0]); FMA2(acc[1][1], av.y, b1, acc[1][1]);
        FMA2(acc[1][2], av.y, b2, acc[1][2]); FMA2(acc[1][3], av.y, b3, acc[1][3]);
    }

    if (ng < 9) {
#pragma unroll
        for (int p = 0; p < 2; p++) {
            float lo[4], hi[4];
#pragma unroll
            for (int c = 0; c < 4; c++) UNPK2(lo[c], hi[c], acc[p][c]);
            long r0 = ((long)b*SEQL + l0 + lb + 2*p) * 36 + (ng << 2);
            *(float4*)&xd[r0]      = make_float4(lo[0], lo[1], lo[2], lo[3]);
            *(float4*)&xd[r0 + 36] = make_float4(hi[0], hi[1], hi[2], hi[3]);
        }
    }
}

// ---------------- grid barrier (all 512 blocks resident by construction) ----------------
__device__ __forceinline__ void gridbar(int tid) {
    __syncthreads();
    if (tid == 0) {
        __threadfence();
        unsigned t = atomicAdd(&g_ctr, 1u);
        unsigned target = (t & ~511u) + 512u;
        volatile unsigned* p = &g_ctr;
        while ((int)(*p - target) < 0) __nanosleep(64);
    }
    __syncthreads();
    __threadfence();
}

// ---------------- fused selective scan: pass1 + combine + pass3 ----------------
// grid (NCH, BATCH) = 512 blocks x 128 thr; smem ~54KB -> 4 blocks/SM, all resident.
__global__ __launch_bounds__(128) void scanf_k(const float* __restrict__ u,
                                               const float* __restrict__ xdbl,
                                               const float* __restrict__ xr,
                                               const float* __restrict__ Ap,
                                               const float* __restrict__ dtw,
                                               const float* __restrict__ dtb,
                                               const float* __restrict__ Dp,
                                               float* __restrict__ hp,
                                               float* __restrict__ yg,
                                               const int* __restrict__ flagp) {
    __shared__ float xds[TCH*36];
    __shared__ float uss[TCH*129];
    __shared__ float dts[TCH*128];   // caches softplus(dt)
    __shared__ float ys[TCH*129];
    int d = threadIdx.x;
    int c = blockIdx.x, b = blockIdx.y;
    long lc = (long)b*SEQL + c*TCH;
    for (int e = d; e < TCH*36; e += 128) xds[e] = xdbl[lc*36 + e];
    for (int e = d; e < TCH*DIN; e += 128) {
        int d2 = e >> 5, t = e & 31;
        uss[t*129 + d2] = u[((long)b*DIN + d2)*SEQL + c*TCH + t];
    }
    float4 w = *(const float4*)&dtw[d*4];
    float bias = __ldg(&dtb[d]);
    float Dd = __ldg(&Dp[d]);
    int structured = *flagp;
    float A0 = Ap[d*NST];
    float* o = hp + (((long)b*NCH + c)*DIN + d)*32;
    __syncthreads();

    // ---- pass 1: local scan from h=0; cache softplus(dt) ----
    float S = 0.f;
    if (structured) {
        u64 h2[8];
#pragma unroll
        for (int p = 0; p < 8; p++) h2[p] = 0ULL;
        for (int t = 0; t < TCH; t++) {
            const float* xt = xds + t*36;
            float dt = fmaf(xt[0], w.x, fmaf(xt[1], w.y, fmaf(xt[2], w.z, fmaf(xt[3], w.w, bias))));
            dt = softplusf(dt);
            dts[t*128 + d] = dt;
            S += dt;
            float du = dt * uss[t*129 + d];
            float r = __expf(dt * A0);
            float r2 = r * r;
            u64 a2, rr2, du2;
            PKP(a2, r, r2); PK1(rr2, r2); PK1(du2, du);
#pragma unroll
            for (int p = 0; p < 8; p++) {
                u64 bp = *(const u64*)&xt[4 + 2*p];
                u64 m;
                MUL2(m, du2, bp);
                FMA2(h2[p], a2, h2[p], m);
                if (p < 7) MUL2(a2, a2, rr2);
            }
        }
#pragma unroll
        for (int p = 0; p < 8; p++) *(u64*)&o[2*p] = h2[p];
        float q = __expf(S * A0), qc = q;
#pragma unroll
        for (int n = 0; n < NST; n++) { o[16 + n] = qc; qc *= q; }
    } else {
        float Ar[NST], h[NST];
#pragma unroll
        for (int n = 0; n < NST; n++) { Ar[n] = Ap[d*NST + n]; h[n] = 0.f; }
        for (int t = 0; t < TCH; t++) {
            const float* xt = xds + t*36;
            float dt = fmaf(xt[0], w.x, fmaf(xt[1], w.y, fmaf(xt[2], w.z, fmaf(xt[3], w.w, bias))));
            dt = softplusf(dt);
            dts[t*128 + d] = dt;
            S += dt;
            float du = dt * uss[t*129 + d];
#pragma unroll
            for (int n = 0; n < NST; n++) {
                float a = __expf(dt * Ar[n]);
                h[n] = fmaf(a, h[n], du * xt[4 + n]);
            }
        }
#pragma unroll
        for (int n = 0; n < NST; n++) { o[n] = h[n]; o[16 + n] = __expf(S * Ar[n]); }
    }

    gridbar(d);

    // ---- pass 2: sequential chunk combine on 64 blocks (8192 threads) ----
    int bid = b*NCH + c;
    if (bid < 64) {
        int widx = bid*128 + d;
        int b2 = widx >> 11;
        int dn = widx & 2047;
        int off = ((dn >> 4) << 5) + (dn & 15);
        long base = (long)b2 * NCH * (DIN*32) + off;
        float H = 0.f;
        for (int cc = 0; cc < NCH; cc++) {
            float he = hp[base];
            float p  = hp[base + 16];
            hp[base] = H;
            H = fmaf(p, H, he);
            base += DIN*32;
        }
    }

    gridbar(d);

    // ---- pass 3: replay from H_init; y = C.h + u*D; gate by silu(res) ----
    const float* hi = o;
    if (structured) {
        u64 h2[8];
#pragma unroll
        for (int p = 0; p < 8; p++) h2[p] = *(const u64*)&hi[2*p];
        for (int t = 0; t < TCH; t++) {
            const float* xt = xds + t*36;
            float dt = dts[t*128 + d];
            float ut = uss[t*129 + d];
            float du = dt * ut;
            float r = __expf(dt * A0);
            float r2 = r * r;
            u64 a2, rr2, du2, y2 = 0ULL;
            PKP(a2, r, r2); PK1(rr2, r2); PK1(du2, du);
#pragma unroll
            for (int p = 0; p < 8; p++) {
                u64 bp = *(const u64*)&xt[4 + 2*p];
                u64 cp = *(const u64*)&xt[20 + 2*p];
                u64 m;
                MUL2(m, du2, bp);
                FMA2(h2[p], a2, h2[p], m);
                FMA2(y2, h2[p], cp, y2);
                if (p < 7) MUL2(a2, a2, rr2);
            }
            float ylo, yhi;
            UNPK2(ylo, yhi, y2);
            float rt = xr[(lc + t)*256 + 128 + d];
            ys[t*129 + d] = fmaf(ut, Dd, ylo + yhi) * siluf(rt);
        }
    } else {
        float Ar[NST], h[NST];
#pragma unroll
        for (int n = 0; n < NST; n++) { Ar[n] = Ap[d*NST + n]; h[n] = hi[n]; }
        for (int t = 0; t < TCH; t++) {
            const float* xt = xds + t*36;
            float dt = dts[t*128 + d];
            float ut = uss[t*129 + d];
            float du = dt * ut;
            float y = 0.f;
#pragma unroll
            for (int n = 0; n < NST; n++) {
                float a = __expf(dt * Ar[n]);
                h[n] = fmaf(a, h[n], du * xt[4 + n]);
                y = fmaf(h[n], xt[20 + n], y);
            }
            float rt = xr[(lc + t)*256 + 128 + d];
            ys[t*129 + d] = fmaf(ut, Dd, y) * siluf(rt);
        }
    }
    __syncthreads();
    for (int e = d; e < TCH*DIN; e += 128) {
        int d2 = e >> 5, t = e & 31;
        yg[((long)b*DIN + d2)*SEQL + c*TCH + t] = ys[t*129 + d2];
    }
}

// ---------------- host ----------------
extern "C" void kernel_launch(void* const* d_in, const int* in_sizes, int n_in,
                              void* d_out, int out_size) {
    const float* x1 = (const float*)d_in[0];
    float* out = (float*)d_out;

    float *xr, *u, *xd, *hp, *yg, *xmid, *w1t, *wxt, *wot, *Ab;
    int* Afl;
    cudaGetSymbolAddress((void**)&xr,   g_xr);
    cudaGetSymbolAddress((void**)&u,    g_u);
    cudaGetSymbolAddress((void**)&xd,   g_xdbl);
    cudaGetSymbolAddress((void**)&hp,   g_hp);
    cudaGetSymbolAddress((void**)&yg,   g_yg);
    cudaGetSymbolAddress((void**)&xmid, g_xmid);
    cudaGetSymbolAddress((void**)&w1t,  g_w1t);
    cudaGetSymbolAddress((void**)&wxt,  g_wxt);
    cudaGetSymbolAddress((void**)&wot,  g_wot);
    cudaGetSymbolAddress((void**)&Ab,   g_Ab);
    cudaGetSymbolAddress((void**)&Afl,  g_Afl);

    prep_k<<<dim3(136, 2), 256>>>(
        (const float*)d_in[1], (const float*)d_in[4], (const float*)d_in[9], (const float*)d_in[7],
        (const float*)d_in[10], (const float*)d_in[13], (const float*)d_in[18], (const float*)d_in[16],
        w1t, wxt, wot, Ab);
    chkA_k<<<2, 256>>>(Ab, Ab + 2048, Afl);

    const int GSM  = 33280;                            // gemm_k dynamic smem
    const int CSM  = (67*132 + 128*64 + 128*US_P) * 4; // cxp_k dynamic smem (~103KB)
    cudaFuncSetAttribute(cxp_k, cudaFuncAttributeMaxDynamicSharedMemorySize, CSM);

    for (int m = 0; m < 2; m++) {
        const float* cw  = (const float*)d_in[1 + 9*m + 1];
        const float* cb  = (const float*)d_in[1 + 9*m + 2];
        const float* dtw = (const float*)d_in[1 + 9*m + 4];
        const float* dtb = (const float*)d_in[1 + 9*m + 5];
        const float* Dp  = (const float*)d_in[1 + 9*m + 7];
        const float* lng = (const float*)d_in[19 + 2*m];
        const float* lnb = (const float*)d_in[20 + 2*m];
        const float* Abm = Ab + m*2048;
        const int*   flm = Afl + m;

        const float* Xin = (m == 0) ? x1 : xmid;      // k-major [b][64][4096]
        float* gout = (m == 0) ? xmid : out;          // k-major [b][64][4096]

        // in_proj: K=64, N=256 -> xr row-major [l][256]
        gemm_k<<<dim3(SEQL/64, 4, BATCH), 256, GSM>>>(
            Xin, w1t + m*16384, xr, 64, 256, 256, 0, nullptr, nullptr);
        // FUSED conv+silu + x_proj -> u [b][128][4096] and xd [l][36]
        cxp_k<<<dim3(SEQL/64, BATCH), 256, CSM>>>(
            xr, cw, cb, wxt + m*8192, u, xd);
        // fused chunked selective scan (pass1 + combine + pass3)
        scanf_k<<<dim3(NCH, BATCH), DIN>>>(u, xd, xr, Abm, dtw, dtb, Dp, hp, yg, flm);
        // out_proj + LayerNorm + transposed write
        gemm_k<<<dim3(SEQL/64, 1, BATCH), 256, GSM>>>(
            yg, wot + m*8192, gout, 128, 64, 64, 2, lng, lnb);
    }
}

// round 11
// speedup vs baseline: 1.0442x; 1.0442x over previous
#include <cuda_runtime.h>

#define BATCH 4
#define SEQL  4096
#define DIN   128
#define NST   16
#define TCH   32
#define NCH   128   /* SEQL / TCH */

typedef unsigned long long u64;

#define FMA2(d, a, b, c) asm("fma.rn.f32x2 %0, %1, %2, %3;" : "=l"(d) : "l"(a), "l"(b), "l"(c))
#define MUL2(d, a, b)    asm("mul.rn.f32x2 %0, %1, %2;" : "=l"(d) : "l"(a), "l"(b))
#define UNPK2(x, y, in)  asm("mov.b64 {%0, %1}, %2;" : "=f"(x), "=f"(y) : "l"(in))
#define PK1(d, x)        asm("mov.b64 %0, {%1, %1};" : "=l"(d) : "f"(x))
#define PKP(d, x, y)     asm("mov.b64 %0, {%1, %2};" : "=l"(d) : "f"(x), "f"(y))

#define CPA16(dst, src)  asm volatile("cp.async.cg.shared.global [%0], [%1], 16;" :: "r"(dst), "l"(src) : "memory")
#define CPCOM()          asm volatile("cp.async.commit_group;" ::: "memory")
#define CPWAIT1()        asm volatile("cp.async.wait_group 1;" ::: "memory")
#define CPWAIT0()        asm volatile("cp.async.wait_group 0;" ::: "memory")

// ---------------- scratch (device globals; no allocation) ----------------
__device__ float g_xr  [BATCH*SEQL*256];   // in_proj output (u | res), row-major [l][256]
__device__ float g_u   [BATCH*DIN*SEQL];   // silu(conv(u)), k-major [b][d][l]
__device__ float g_xdbl[BATCH*SEQL*36];    // x_proj output, row-major [l][36] (dt4|B16|C16)
__device__ float g_hp  [BATCH*NCH*DIN*32]; // per-chunk [h_end(16)|P(16)] -> H_init
__device__ float g_yg  [BATCH*DIN*SEQL];   // gated scan output, k-major [b][d][l]
__device__ float g_xmid[BATCH*64*SEQL];    // between mambas, k-major [b][c][l]
__device__ float g_w1t [2][64*256];        // in_proj W transposed [k][n]
__device__ float g_wxt [2][128*64];        // x_proj W transposed, zero-padded to 64
__device__ float g_wot [2][128*64];        // out_proj W transposed
__device__ float g_Ab  [2][DIN*NST];       // A = -exp(Alog)
__device__ int   g_Afl [2];                // 1 if A[d][n] == (n+1)*A[d][0]
__device__ unsigned g_ctr = 0;             // grid-barrier ticket counter (monotonic)

__device__ __forceinline__ float softplusf(float x) {
    return x > 15.f ? x : __logf(1.f + __expf(x));
}
__device__ __forceinline__ float siluf(float x) {
    return x / (1.f + __expf(-x));
}

// ---------------- prep: both mambas in one launch ----------------
__global__ void prep_k(const float* __restrict__ iw0, const float* __restrict__ xp0,
                       const float* __restrict__ ow0, const float* __restrict__ al0,
                       const float* __restrict__ iw1, const float* __restrict__ xp1,
                       const float* __restrict__ ow1, const float* __restrict__ al1,
                       float* __restrict__ w1t, float* __restrict__ wxt,
                       float* __restrict__ wot, float* __restrict__ Ab) {
    int m = blockIdx.y;
    const float* in_w  = m ? iw1 : iw0;
    const float* xproj = m ? xp1 : xp0;
    const float* out_w = m ? ow1 : ow0;
    const float* Alog  = m ? al1 : al0;
    float* w1 = w1t + m*16384;
    float* wx = wxt + m*8192;
    float* wo = wot + m*8192;
    float* Am = Ab  + m*2048;
    int idx = blockIdx.x * 256 + threadIdx.x;
    if (idx < 16384) { int k = idx >> 8, n = idx & 255; w1[idx] = in_w[n*64 + k]; return; }
    idx -= 16384;
    if (idx < 8192)  { int k = idx >> 6, n = idx & 63; wx[idx] = (n < 36) ? xproj[n*128 + k] : 0.f; return; }
    idx -= 8192;
    if (idx < 8192)  { int k = idx >> 6, n = idx & 63; wo[idx] = out_w[n*128 + k]; return; }
    idx -= 8192;
    if (idx < 2048)  Am[idx] = -expf(Alog[idx]);
}

__global__ void chkA_k(const float* __restrict__ A0, const float* __restrict__ A1,
                       int* __restrict__ fl) {
    const float* A = blockIdx.x ? A1 : A0;
    __shared__ int ok;
    if (threadIdx.x == 0) ok = 1;
    __syncthreads();
    int bad = 0;
    for (int e = threadIdx.x; e < DIN*NST; e += 256) {
        int d = e >> 4, n = e & 15;
        float expv = (float)(n + 1) * A[d*16];
        if (fabsf(A[e] - expv) > 1e-5f * fabsf(expv) + 1e-20f) bad = 1;
    }
    if (bad) atomicAnd(&ok, 0);
    __syncthreads();
    if (threadIdx.x == 0) fl[blockIdx.x] = ok;
}

// ---------------- pipelined GEMM: X k-major [b][K][4096]; tile 64L x 64N ----------------
// 2-stage cp.async over k-tiles of 32. 4L x 4N per thread (2 f32x2 row-pairs).
// epi: 0 = row-major [l][Nout] at col n0; 1 = cols<36 to [l][36];
//      2 = LayerNorm over 64 cols + transposed write [b][64][4096].
__global__ __launch_bounds__(256) void gemm_k(
    const float* __restrict__ X, const float* __restrict__ Wt, float* __restrict__ Out,
    int K, int Nld, int Nout, int epi,
    const float* __restrict__ lng, const float* __restrict__ lnb)
{
    extern __shared__ float sm[];  // [2][32*64] X | [2][32*64] W  (epilogue staging reuse)
    int tid = threadIdx.x;
    int l0 = blockIdx.x << 6;
    int n0 = blockIdx.y << 6;
    int b  = blockIdx.z;
    const float* Xb = X + (long)b * K * SEQL;
    int lj = tid >> 4, ng = tid & 15;
    int lb = lj << 2;
    unsigned smb = (unsigned)__cvta_generic_to_shared(sm);
    int ntiles = K >> 5;

    // issue tile 0 into stage 0
    {
#pragma unroll
        for (int i = 0; i < 2; i++) {
            int e = tid + (i << 8);
            int k = e >> 4, lq = e & 15;
            CPA16(smb + (((k << 6) + (lq << 2)) << 2),
                  Xb + (long)k * SEQL + l0 + (lq << 2));
        }
#pragma unroll
        for (int i = 0; i < 2; i++) {
            int e = tid + (i << 8);
            int k = e >> 4, nq = e & 15;
            CPA16(smb + 16384u + (((k << 6) + (nq << 2)) << 2),
                  Wt + (long)k * Nld + n0 + (nq << 2));
        }
        CPCOM();
    }

    u64 acc[2][4];
#pragma unroll
    for (int p = 0; p < 2; p++)
#pragma unroll
        for (int c = 0; c < 4; c++) acc[p][c] = 0ULL;

    for (int tt = 0; tt < ntiles; tt++) {
        int s = tt & 1;
        if (tt + 1 < ntiles) {
            int kofs = (tt + 1) << 5;
            int s2 = s ^ 1;
#pragma unroll
            for (int i = 0; i < 2; i++) {
                int e = tid + (i << 8);
                int k = e >> 4, lq = e & 15;
                CPA16(smb + (((s2 << 11) + (k << 6) + (lq << 2)) << 2),
                      Xb + (long)(kofs + k) * SEQL + l0 + (lq << 2));
            }
#pragma unroll
            for (int i = 0; i < 2; i++) {
                int e = tid + (i << 8);
                int k = e >> 4, nq = e & 15;
                CPA16(smb + 16384u + (((s2 << 11) + (k << 6) + (nq << 2)) << 2),
                      Wt + (long)(kofs + k) * Nld + n0 + (nq << 2));
            }
            CPCOM();
            CPWAIT1();
        } else {
            CPWAIT0();
        }
        __syncthreads();
        const float* xs = sm + (s << 11);
        const float* ws = sm + 4096 + (s << 11);
#pragma unroll 8
        for (int kk = 0; kk < 32; kk++) {
            ulonglong2 av = *(const ulonglong2*)&xs[(kk << 6) + lb];   // rows (0,1),(2,3)
            float4 wv = *(const float4*)&ws[(kk << 6) + (ng << 2)];
            u64 b0, b1, b2, b3;
            PK1(b0, wv.x); PK1(b1, wv.y); PK1(b2, wv.z); PK1(b3, wv.w);
            FMA2(acc[0][0], av.x, b0, acc[0][0]); FMA2(acc[0][1], av.x, b1, acc[0][1]);
            FMA2(acc[0][2], av.x, b2, acc[0][2]); FMA2(acc[0][3], av.x, b3, acc[0][3]);
            FMA2(acc[1][0], av.y, b0, acc[1][0]); FMA2(acc[1][1], av.y, b1, acc[1][1]);
            FMA2(acc[1][2], av.y, b2, acc[1][2]); FMA2(acc[1][3], av.y, b3, acc[1][3]);
        }
        __syncthreads();
    }

    if (epi == 0) {
#pragma unroll
        for (int p = 0; p < 2; p++) {
            float lo[4], hi[4];
#pragma unroll
            for (int c = 0; c < 4; c++) UNPK2(lo[c], hi[c], acc[p][c]);
            long r0 = ((long)b*SEQL + l0 + lb + 2*p) * Nout + n0 + (ng << 2);
            *(float4*)&Out[r0]        = make_float4(lo[0], lo[1], lo[2], lo[3]);
            *(float4*)&Out[r0 + Nout] = make_float4(hi[0], hi[1], hi[2], hi[3]);
        }
    } else if (epi == 1) {
        if (ng < 9) {
#pragma unroll
            for (int p = 0; p < 2; p++) {
                float lo[4], hi[4];
#pragma unroll
                for (int c = 0; c < 4; c++) UNPK2(lo[c], hi[c], acc[p][c]);
                long r0 = ((long)b*SEQL + l0 + lb + 2*p) * 36 + (ng << 2);
                *(float4*)&Out[r0]      = make_float4(lo[0], lo[1], lo[2], lo[3]);
                *(float4*)&Out[r0 + 36] = make_float4(hi[0], hi[1], hi[2], hi[3]);
            }
        }
    } else {
        // LayerNorm over 64 cols + transposed coalesced write (n0==0)
        float* st  = sm;          // [64 l][65]
        float* st2 = sm + 4160;   // [64 n][65] transposed
#pragma unroll
        for (int p = 0; p < 2; p++) {
#pragma unroll
            for (int c = 0; c < 4; c++) {
                float lo, hi;
                UNPK2(lo, hi, acc[p][c]);
                st[(lb + 2*p)*65 + (ng << 2) + c]     = lo;
                st[(lb + 2*p + 1)*65 + (ng << 2) + c] = hi;
            }
        }
        __syncthreads();
        int row = tid >> 2, q = tid & 3;
        float v[16], s = 0.f, s2 = 0.f;
#pragma unroll
        for (int j = 0; j < 16; j++) {
            float x = st[row*65 + q*16 + j];
            v[j] = x; s += x; s2 += x * x;
        }
        s  += __shfl_xor_sync(0xffffffffu, s, 1);
        s2 += __shfl_xor_sync(0xffffffffu, s2, 1);
        s  += __shfl_xor_sync(0xffffffffu, s, 2);
        s2 += __shfl_xor_sync(0xffffffffu, s2, 2);
        float mean = s * 0.015625f;
        float var  = s2 * 0.015625f - mean * mean;
        float rstd = rsqrtf(var + 1e-5f);
#pragma unroll
        for (int j = 0; j < 16; j++) {
            int n = q*16 + j;
            st2[n*65 + row] = (v[j] - mean) * rstd * __ldg(&lng[n]) + __ldg(&lnb[n]);
        }
        __syncthreads();
        int n2 = tid >> 2, lq = tid & 3;
#pragma unroll
        for (int i = 0; i < 4; i++) {
            int l = (lq << 4) + (i << 2);
            float4 o4 = make_float4(st2[n2*65 + l], st2[n2*65 + l + 1],
                                    st2[n2*65 + l + 2], st2[n2*65 + l + 3]);
            *(float4*)&Out[((long)b*64 + n2)*SEQL + l0 + l] = o4;
        }
    }
}

// ---------------- causal depthwise conv (k=4) + silu; out k-major [b][d][l] ----------------
__global__ __launch_bounds__(256) void conv_silu_k(const float* __restrict__ xr,
                                                   const float* __restrict__ cw,
                                                   const float* __restrict__ cb,
                                                   float* __restrict__ u) {
    __shared__ float sx[35*132];
    __shared__ float su[32*129];
    int tid = threadIdx.x;
    int l0 = blockIdx.x << 5;
    int b  = blockIdx.y;
    for (int e = tid; e < 35*32; e += 256) {
        int row = e >> 5, d4 = e & 31;
        int lg = l0 - 3 + row;
        float4 v = (lg >= 0) ? *(const float4*)&xr[((long)b*SEQL + lg)*256 + (d4 << 2)]
                             : make_float4(0.f, 0.f, 0.f, 0.f);
        *(float4*)&sx[row*132 + (d4 << 2)] = v;
    }
    __syncthreads();
    int d = tid >> 1, half = tid & 1;
    float4 w = *(const float4*)&cw[d*4];
    float bias = __ldg(&cb[d]);
#pragma unroll
    for (int j = 0; j < 16; j++) {
        int l = half*16 + j;
        float s = bias + w.w*sx[(l+3)*132 + d] + w.z*sx[(l+2)*132 + d]
                       + w.y*sx[(l+1)*132 + d] + w.x*sx[l*132 + d];
        su[l*129 + d] = siluf(s);
    }
    __syncthreads();
    for (int e = tid; e < 1024; e += 256) {
        int d2 = e >> 3, l4 = e & 7;
        int lc = l4 << 2;
        float4 o4 = make_float4(su[lc*129 + d2],       su[(lc+1)*129 + d2],
                                su[(lc+2)*129 + d2],   su[(lc+3)*129 + d2]);
        *(float4*)&u[((long)b*DIN + d2)*SEQL + l0 + lc] = o4;
    }
}

// ---------------- grid barrier (all 512 blocks resident by construction) ----------------
__device__ __forceinline__ void gridbar(int tid) {
    __syncthreads();
    if (tid == 0) {
        __threadfence();
        unsigned t = atomicAdd(&g_ctr, 1u);
        unsigned target = (t & ~511u) + 512u;
        volatile unsigned* p = &g_ctr;
        while ((int)(*p - target) < 0) __nanosleep(64);
    }
    __syncthreads();
    __threadfence();
}

// ---------------- fused selective scan: pass1 + segmented combine + pass3 ----------------
// grid (NCH, BATCH) = 512 blocks x 128 thr; smem ~54KB -> 4 blocks/SM, all resident.
__global__ __launch_bounds__(128) void scanf_k(const float* __restrict__ u,
                                               const float* __restrict__ xdbl,
                                               const float* __restrict__ xr,
                                               const float* __restrict__ Ap,
                                               const float* __restrict__ dtw,
                                               const float* __restrict__ dtb,
                                               const float* __restrict__ Dp,
                                               float* __restrict__ hp,
                                               float* __restrict__ yg,
                                               const int* __restrict__ flagp) {
    __shared__ float xds[TCH*36];
    __shared__ float uss[TCH*129];
    __shared__ float dts[TCH*128];   // caches softplus(dt)
    __shared__ float ys[TCH*129];
    int d = threadIdx.x;
    int c = blockIdx.x, b = blockIdx.y;
    long lc = (long)b*SEQL + c*TCH;
    for (int e = d; e < TCH*36; e += 128) xds[e] = xdbl[lc*36 + e];
    for (int e = d; e < TCH*DIN; e += 128) {
        int d2 = e >> 5, t = e & 31;
        uss[t*129 + d2] = u[((long)b*DIN + d2)*SEQL + c*TCH + t];
    }
    float4 w = *(const float4*)&dtw[d*4];
    float bias = __ldg(&dtb[d]);
    float Dd = __ldg(&Dp[d]);
    int structured = *flagp;
    float A0 = Ap[d*NST];
    float* o = hp + (((long)b*NCH + c)*DIN + d)*32;
    __syncthreads();

    // ---- pass 1: local scan from h=0; cache softplus(dt) ----
    float S = 0.f;
    if (structured) {
        u64 h2[8];
#pragma unroll
        for (int p = 0; p < 8; p++) h2[p] = 0ULL;
        for (int t = 0; t < TCH; t++) {
            const float* xt = xds + t*36;
            float dt = fmaf(xt[0], w.x, fmaf(xt[1], w.y, fmaf(xt[2], w.z, fmaf(xt[3], w.w, bias))));
            dt = softplusf(dt);
            dts[t*128 + d] = dt;
            S += dt;
            float du = dt * uss[t*129 + d];
            float r = __expf(dt * A0);
            float r2 = r * r;
            u64 a2, rr2, du2;
            PKP(a2, r, r2); PK1(rr2, r2); PK1(du2, du);
#pragma unroll
            for (int p = 0; p < 8; p++) {
                u64 bp = *(const u64*)&xt[4 + 2*p];
                u64 m;
                MUL2(m, du2, bp);
                FMA2(h2[p], a2, h2[p], m);
                if (p < 7) MUL2(a2, a2, rr2);
            }
        }
#pragma unroll
        for (int p = 0; p < 8; p++) *(u64*)&o[2*p] = h2[p];
        float q = __expf(S * A0), qc = q;
#pragma unroll
        for (int n = 0; n < NST; n++) { o[16 + n] = qc; qc *= q; }
    } else {
        float Ar[NST], h[NST];
#pragma unroll
        for (int n = 0; n < NST; n++) { Ar[n] = Ap[d*NST + n]; h[n] = 0.f; }
        for (int t = 0; t < TCH; t++) {
            const float* xt = xds + t*36;
            float dt = fmaf(xt[0], w.x, fmaf(xt[1], w.y, fmaf(xt[2], w.z, fmaf(xt[3], w.w, bias))));
            dt = softplusf(dt);
            dts[t*128 + d] = dt;
            S += dt;
            float du = dt * uss[t*129 + d];
#pragma unroll
            for (int n = 0; n < NST; n++) {
                float a = __expf(dt * Ar[n]);
                h[n] = fmaf(a, h[n], du * xt[4 + n]);
            }
        }
#pragma unroll
        for (int n = 0; n < NST; n++) { o[n] = h[n]; o[16 + n] = __expf(S * Ar[n]); }
    }

    gridbar(d);

    // ---- pass 2: segmented chunk combine; ALL 65536 threads.
    //      8 threads per (b,d,n) state; 16 chunks each; shfl scan across segments. ----
    {
        int g = (b*NCH + c)*128 + d;       // 0..65535
        int s = g >> 3, sg = g & 7;        // state, segment
        int b2 = s >> 11;
        int dn = s & 2047;
        int off = ((dn >> 4) << 5) + (dn & 15);
        long base = (long)b2 * NCH * (DIN*32) + off + (long)sg * 16 * (DIN*32);
        float he[16], pp[16];
        float H = 0.f, P = 1.f;
#pragma unroll
        for (int j = 0; j < 16; j++) {
            he[j] = hp[base + (long)j*(DIN*32)];
            pp[j] = hp[base + (long)j*(DIN*32) + 16];
        }
#pragma unroll
        for (int j = 0; j < 16; j++) {
            H = fmaf(pp[j], H, he[j]);
            P *= pp[j];
        }
        // inclusive Hillis-Steele scan over the 8 segments (associative combine)
#pragma unroll
        for (int k = 1; k < 8; k <<= 1) {
            float Hu = __shfl_up_sync(0xffffffffu, H, k, 8);
            float Pu = __shfl_up_sync(0xffffffffu, P, k, 8);
            if (sg >= k) { H = fmaf(P, Hu, H); P *= Pu; }
        }
        // exclusive prefix = H of previous segments
        float Hx = __shfl_up_sync(0xffffffffu, H, 1, 8);
        if (sg == 0) Hx = 0.f;
        // replay from registers, writing per-chunk H_init
        float Hc = Hx;
#pragma unroll
        for (int j = 0; j < 16; j++) {
            hp[base + (long)j*(DIN*32)] = Hc;
            Hc = fmaf(pp[j], Hc, he[j]);
        }
    }

    gridbar(d);

    // ---- pass 3: replay from H_init; y = C.h + u*D; gate by silu(res) ----
    const float* hi = o;
    if (structured) {
        u64 h2[8];
#pragma unroll
        for (int p = 0; p < 8; p++) h2[p] = *(const u64*)&hi[2*p];
        for (int t = 0; t < TCH; t++) {
            const float* xt = xds + t*36;
            float dt = dts[t*128 + d];
            float ut = uss[t*129 + d];
            float du = dt * ut;
            float r = __expf(dt * A0);
            float r2 = r * r;
            u64 a2, rr2, du2, y2 = 0ULL;
            PKP(a2, r, r2); PK1(rr2, r2); PK1(du2, du);
#pragma unroll
            for (int p = 0; p < 8; p++) {
                u64 bp = *(const u64*)&xt[4 + 2*p];
                u64 cp = *(const u64*)&xt[20 + 2*p];
                u64 m;
                MUL2(m, du2, bp);
                FMA2(h2[p], a2, h2[p], m);
                FMA2(y2, h2[p], cp, y2);
                if (p < 7) MUL2(a2, a2, rr2);
            }
            float ylo, yhi;
            UNPK2(ylo, yhi, y2);
            float rt = xr[(lc + t)*256 + 128 + d];
            ys[t*129 + d] = fmaf(ut, Dd, ylo + yhi) * siluf(rt);
        }
    } else {
        float Ar[NST], h[NST];
#pragma unroll
        for (int n = 0; n < NST; n++) { Ar[n] = Ap[d*NST + n]; h[n] = hi[n]; }
        for (int t = 0; t < TCH; t++) {
            const float* xt = xds + t*36;
            float dt = dts[t*128 + d];
            float ut = uss[t*129 + d];
            float du = dt * ut;
            float y = 0.f;
#pragma unroll
            for (int n = 0; n < NST; n++) {
                float a = __expf(dt * Ar[n]);
                h[n] = fmaf(a, h[n], du * xt[4 + n]);
                y = fmaf(h[n], xt[20 + n], y);
            }
            float rt = xr[(lc + t)*256 + 128 + d];
            ys[t*129 + d] = fmaf(ut, Dd, y) * siluf(rt);
        }
    }
    __syncthreads();
    for (int e = d; e < TCH*DIN; e += 128) {
        int d2 = e >> 5, t = e & 31;
        yg[((long)b*DIN + d2)*SEQL + c*TCH + t] = ys[t*129 + d2];
    }
}

// ---------------- host ----------------
extern "C" void kernel_launch(void* const* d_in, const int* in_sizes, int n_in,
                              void* d_out, int out_size) {
    const float* x1 = (const float*)d_in[0];
    float* out = (float*)d_out;

    float *xr, *u, *xd, *hp, *yg, *xmid, *w1t, *wxt, *wot, *Ab;
    int* Afl;
    cudaGetSymbolAddress((void**)&xr,   g_xr);
    cudaGetSymbolAddress((void**)&u,    g_u);
    cudaGetSymbolAddress((void**)&xd,   g_xdbl);
    cudaGetSymbolAddress((void**)&hp,   g_hp);
    cudaGetSymbolAddress((void**)&yg,   g_yg);
    cudaGetSymbolAddress((void**)&xmid, g_xmid);
    cudaGetSymbolAddress((void**)&w1t,  g_w1t);
    cudaGetSymbolAddress((void**)&wxt,  g_wxt);
    cudaGetSymbolAddress((void**)&wot,  g_wot);
    cudaGetSymbolAddress((void**)&Ab,   g_Ab);
    cudaGetSymbolAddress((void**)&Afl,  g_Afl);

    prep_k<<<dim3(136, 2), 256>>>(
        (const float*)d_in[1], (const float*)d_in[4], (const float*)d_in[9], (const float*)d_in[7],
        (const float*)d_in[10], (const float*)d_in[13], (const float*)d_in[18], (const float*)d_in[16],
        w1t, wxt, wot, Ab);
    chkA_k<<<2, 256>>>(Ab, Ab + 2048, Afl);

    const int GSM = 33280;

    for (int m = 0; m < 2; m++) {
        const float* cw  = (const float*)d_in[1 + 9*m + 1];
        const float* cb  = (const float*)d_in[1 + 9*m + 2];
        const float* dtw = (const float*)d_in[1 + 9*m + 4];
        const float* dtb = (const float*)d_in[1 + 9*m + 5];
        const float* Dp  = (const float*)d_in[1 + 9*m + 7];
        const float* lng = (const float*)d_in[19 + 2*m];
        const float* lnb = (const float*)d_in[20 + 2*m];
        const float* Abm = Ab + m*2048;
        const int*   flm = Afl + m;

        const float* Xin = (m == 0) ? x1 : xmid;      // k-major [b][64][4096]
        float* gout = (m == 0) ? xmid : out;          // k-major [b][64][4096]

        // in_proj: K=64, N=256 -> xr row-major [l][256]
        gemm_k<<<dim3(SEQL/64, 4, BATCH), 256, GSM>>>(
            Xin, w1t + m*16384, xr, 64, 256, 256, 0, nullptr, nullptr);
        // conv + silu -> u [b][128][4096]
        conv_silu_k<<<dim3(SEQL/32, BATCH), 256>>>(xr, cw, cb, u);
        // x_proj: K=128, N=64(36) -> xd row-major
        gemm_k<<<dim3(SEQL/64, 1, BATCH), 256, GSM>>>(
            u, wxt + m*8192, xd, 128, 64, 36, 1, nullptr, nullptr);
        // fused chunked selective scan (pass1 + segmented combine + pass3)
        scanf_k<<<dim3(NCH, BATCH), DIN>>>(u, xd, xr, Abm, dtw, dtb, Dp, hp, yg, flm);
        // out_proj + LayerNorm + transposed write
        gemm_k<<<dim3(SEQL/64, 1, BATCH), 256, GSM>>>(
            yg, wot + m*8192, gout, 128, 64, 64, 2, lng, lnb);
    }
}

// round 12
// speedup vs baseline: 1.0587x; 1.0138x over previous
#include <cuda_runtime.h>

#define BATCH 4
#define SEQL  4096
#define DIN   128
#define NST   16
#define TCH   32
#define NCH   128   /* SEQL / TCH */

typedef unsigned long long u64;

#define FMA2(d, a, b, c) asm("fma.rn.f32x2 %0, %1, %2, %3;" : "=l"(d) : "l"(a), "l"(b), "l"(c))
#define MUL2(d, a, b)    asm("mul.rn.f32x2 %0, %1, %2;" : "=l"(d) : "l"(a), "l"(b))
#define UNPK2(x, y, in)  asm("mov.b64 {%0, %1}, %2;" : "=f"(x), "=f"(y) : "l"(in))
#define PK1(d, x)        asm("mov.b64 %0, {%1, %1};" : "=l"(d) : "f"(x))
#define PKP(d, x, y)     asm("mov.b64 %0, {%1, %2};" : "=l"(d) : "f"(x), "f"(y))

#define CPA16(dst, src)  asm volatile("cp.async.cg.shared.global [%0], [%1], 16;" :: "r"(dst), "l"(src) : "memory")
#define CPCOM()          asm volatile("cp.async.commit_group;" ::: "memory")
#define CPWAIT1()        asm volatile("cp.async.wait_group 1;" ::: "memory")
#define CPWAIT0()        asm volatile("cp.async.wait_group 0;" ::: "memory")

// ---------------- scratch (device globals; no allocation) ----------------
__device__ float g_xr  [BATCH*SEQL*256];   // in_proj output (u | res), row-major [l][256]
__device__ float g_hp  [BATCH*NCH*DIN*32]; // per-chunk [h_end(16)|P(16)] -> H_init
__device__ float g_xmid[BATCH*64*SEQL];    // between mambas, k-major [b][c][l]
__device__ float g_w1t [2][64*256];        // in_proj W transposed [k][n]
__device__ float g_wxt [2][128*64];        // x_proj W transposed, zero-padded to 64
__device__ float g_wot [2][128*64];        // out_proj W transposed
__device__ float g_Ab  [2][DIN*NST];       // A = -exp(Alog)
__device__ int   g_Afl [2];                // 1 if A[d][n] == (n+1)*A[d][0]
__device__ unsigned g_ctr = 0;             // grid-barrier ticket counter (monotonic)

__device__ __forceinline__ float softplusf(float x) {
    return x > 15.f ? x : __logf(1.f + __expf(x));
}
__device__ __forceinline__ float siluf(float x) {
    return x / (1.f + __expf(-x));
}

// ---------------- prep: both mambas in one launch ----------------
__global__ void prep_k(const float* __restrict__ iw0, const float* __restrict__ xp0,
                       const float* __restrict__ ow0, const float* __restrict__ al0,
                       const float* __restrict__ iw1, const float* __restrict__ xp1,
                       const float* __restrict__ ow1, const float* __restrict__ al1,
                       float* __restrict__ w1t, float* __restrict__ wxt,
                       float* __restrict__ wot, float* __restrict__ Ab) {
    int m = blockIdx.y;
    const float* in_w  = m ? iw1 : iw0;
    const float* xproj = m ? xp1 : xp0;
    const float* out_w = m ? ow1 : ow0;
    const float* Alog  = m ? al1 : al0;
    float* w1 = w1t + m*16384;
    float* wx = wxt + m*8192;
    float* wo = wot + m*8192;
    float* Am = Ab  + m*2048;
    int idx = blockIdx.x * 256 + threadIdx.x;
    if (idx < 16384) { int k = idx >> 8, n = idx & 255; w1[idx] = in_w[n*64 + k]; return; }
    idx -= 16384;
    if (idx < 8192)  { int k = idx >> 6, n = idx & 63; wx[idx] = (n < 36) ? xproj[n*128 + k] : 0.f; return; }
    idx -= 8192;
    if (idx < 8192)  { int k = idx >> 6, n = idx & 63; wo[idx] = out_w[n*128 + k]; return; }
    idx -= 8192;
    if (idx < 2048)  Am[idx] = -expf(Alog[idx]);
}

__global__ void chkA_k(const float* __restrict__ A0, const float* __restrict__ A1,
                       int* __restrict__ fl) {
    const float* A = blockIdx.x ? A1 : A0;
    __shared__ int ok;
    if (threadIdx.x == 0) ok = 1;
    __syncthreads();
    int bad = 0;
    for (int e = threadIdx.x; e < DIN*NST; e += 256) {
        int d = e >> 4, n = e & 15;
        float expv = (float)(n + 1) * A[d*16];
        if (fabsf(A[e] - expv) > 1e-5f * fabsf(expv) + 1e-20f) bad = 1;
    }
    if (bad) atomicAnd(&ok, 0);
    __syncthreads();
    if (threadIdx.x == 0) fl[blockIdx.x] = ok;
}

// ---------------- pipelined GEMM (in_proj only): X k-major; tile 64L x 64N ----------------
__global__ __launch_bounds__(256) void gemm_k(
    const float* __restrict__ X, const float* __restrict__ Wt, float* __restrict__ Out,
    int K, int Nld, int Nout)
{
    extern __shared__ float sm[];
    int tid = threadIdx.x;
    int l0 = blockIdx.x << 6;
    int n0 = blockIdx.y << 6;
    int b  = blockIdx.z;
    const float* Xb = X + (long)b * K * SEQL;
    int lj = tid >> 4, ng = tid & 15;
    int lb = lj << 2;
    unsigned smb = (unsigned)__cvta_generic_to_shared(sm);
    int ntiles = K >> 5;

    {
#pragma unroll
        for (int i = 0; i < 2; i++) {
            int e = tid + (i << 8);
            int k = e >> 4, lq = e & 15;
            CPA16(smb + (((k << 6) + (lq << 2)) << 2),
                  Xb + (long)k * SEQL + l0 + (lq << 2));
        }
#pragma unroll
        for (int i = 0; i < 2; i++) {
            int e = tid + (i << 8);
            int k = e >> 4, nq = e & 15;
            CPA16(smb + 16384u + (((k << 6) + (nq << 2)) << 2),
                  Wt + (long)k * Nld + n0 + (nq << 2));
        }
        CPCOM();
    }

    u64 acc[2][4];
#pragma unroll
    for (int p = 0; p < 2; p++)
#pragma unroll
        for (int c = 0; c < 4; c++) acc[p][c] = 0ULL;

    for (int tt = 0; tt < ntiles; tt++) {
        int s = tt & 1;
        if (tt + 1 < ntiles) {
            int kofs = (tt + 1) << 5;
            int s2 = s ^ 1;
#pragma unroll
            for (int i = 0; i < 2; i++) {
                int e = tid + (i << 8);
                int k = e >> 4, lq = e & 15;
                CPA16(smb + (((s2 << 11) + (k << 6) + (lq << 2)) << 2),
                      Xb + (long)(kofs + k) * SEQL + l0 + (lq << 2));
            }
#pragma unroll
            for (int i = 0; i < 2; i++) {
                int e = tid + (i << 8);
                int k = e >> 4, nq = e & 15;
                CPA16(smb + 16384u + (((s2 << 11) + (k << 6) + (nq << 2)) << 2),
                      Wt + (long)(kofs + k) * Nld + n0 + (nq << 2));
            }
            CPCOM();
            CPWAIT1();
        } else {
            CPWAIT0();
        }
        __syncthreads();
        const float* xs = sm + (s << 11);
        const float* ws = sm + 4096 + (s << 11);
#pragma unroll 8
        for (int kk = 0; kk < 32; kk++) {
            ulonglong2 av = *(const ulonglong2*)&xs[(kk << 6) + lb];
            float4 wv = *(const float4*)&ws[(kk << 6) + (ng << 2)];
            u64 b0, b1, b2, b3;
            PK1(b0, wv.x); PK1(b1, wv.y); PK1(b2, wv.z); PK1(b3, wv.w);
            FMA2(acc[0][0], av.x, b0, acc[0][0]); FMA2(acc[0][1], av.x, b1, acc[0][1]);
            FMA2(acc[0][2], av.x, b2, acc[0][2]); FMA2(acc[0][3], av.x, b3, acc[0][3]);
            FMA2(acc[1][0], av.y, b0, acc[1][0]); FMA2(acc[1][1], av.y, b1, acc[1][1]);
            FMA2(acc[1][2], av.y, b2, acc[1][2]); FMA2(acc[1][3], av.y, b3, acc[1][3]);
        }
        __syncthreads();
    }

#pragma unroll
    for (int p = 0; p < 2; p++) {
        float lo[4], hi[4];
#pragma unroll
        for (int c = 0; c < 4; c++) UNPK2(lo[c], hi[c], acc[p][c]);
        long r0 = ((long)b*SEQL + l0 + lb + 2*p) * Nout + n0 + (ng << 2);
        *(float4*)&Out[r0]        = make_float4(lo[0], lo[1], lo[2], lo[3]);
        *(float4*)&Out[r0 + Nout] = make_float4(hi[0], hi[1], hi[2], hi[3]);
    }
}

// ---------------- grid barrier (all 512 blocks resident by construction) ----------------
__device__ __forceinline__ void gridbar(int tid) {
    __syncthreads();
    if (tid == 0) {
        __threadfence();
        unsigned t = atomicAdd(&g_ctr, 1u);
        unsigned target = (t & ~511u) + 512u;
        volatile unsigned* p = &g_ctr;
        while ((int)(*p - target) < 0) __nanosleep(64);
    }
    __syncthreads();
    __threadfence();
}

// ---------------- MEGA: conv+silu + x_proj + scan + out_proj + LayerNorm ----------------
// grid (NCH, BATCH) = 512 blocks x 128 thr; smem 54.3KB -> 4 blocks/SM, all resident.
// smem layout (floats): su[32*129] | ys[32*129] | xds[32*36] | U[4480]
//   U = union of: xh halo (35*128), W k-tile (32*64), LN staging (32*65)
__global__ __launch_bounds__(128, 4) void mega_k(
    const float* __restrict__ xr,
    const float* __restrict__ cw,  const float* __restrict__ cb,
    const float* __restrict__ wxt,
    const float* __restrict__ Ap,
    const float* __restrict__ dtw, const float* __restrict__ dtb,
    const float* __restrict__ Dp,
    const float* __restrict__ wot,
    const float* __restrict__ lng, const float* __restrict__ lnb,
    float* __restrict__ hp,
    float* __restrict__ gout,
    const int* __restrict__ flagp)
{
    extern __shared__ float sm[];
    float* su  = sm;                // [32 t][129]   silu(conv(u))
    float* ys  = sm + 32*129;       // [32 t][129]   scan output (gated)
    float* xds = sm + 2*32*129;     // [32 t][36]
    float* U   = xds + 32*36;       // union region (4480 floats)

    int tid = threadIdx.x;
    int c = blockIdx.x, b = blockIdx.y;
    int lcl = c*TCH;
    long lc = (long)b*SEQL + lcl;

    // ===== Phase A: conv + silu =====
    for (int e = tid; e < 35*32; e += 128) {
        int row = e >> 5, d4 = e & 31;
        int lg = lcl - 3 + row;
        float4 v = (lg >= 0) ? *(const float4*)&xr[((long)b*SEQL + lg)*256 + (d4 << 2)]
                             : make_float4(0.f, 0.f, 0.f, 0.f);
        *(float4*)&U[row*128 + (d4 << 2)] = v;
    }
    __syncthreads();
    {
        int d = tid;
        float4 w = *(const float4*)&cw[d*4];
        float bias = __ldg(&cb[d]);
#pragma unroll 8
        for (int l = 0; l < 32; l++) {
            float s = fmaf(w.x, U[l*128 + d], fmaf(w.y, U[(l+1)*128 + d],
                      fmaf(w.z, U[(l+2)*128 + d], fmaf(w.w, U[(l+3)*128 + d], bias))));
            su[l*129 + d] = siluf(s);
        }
    }
    __syncthreads();   // conv reads of U done; su complete

    // ===== Phase B: x_proj GEMM (32l x 64n x K=128) from su =====
    {
        int lj = tid >> 4, ng = tid & 15;
        int lb = lj << 2;
        u64 acc[2][4];
#pragma unroll
        for (int p = 0; p < 2; p++)
#pragma unroll
            for (int cc = 0; cc < 4; cc++) acc[p][cc] = 0ULL;
        for (int kt = 0; kt < 4; kt++) {
            for (int e = tid; e < 512; e += 128) {
                int k = e >> 4, nq = e & 15;
                *(float4*)&U[k*64 + (nq << 2)] =
                    *(const float4*)&wxt[(kt*32 + k)*64 + (nq << 2)];
            }
            __syncthreads();
#pragma unroll 8
            for (int kk = 0; kk < 32; kk++) {
                int ka = kt*32 + kk;
                float a0 = su[(lb+0)*129 + ka], a1 = su[(lb+1)*129 + ka];
                float a2 = su[(lb+2)*129 + ka], a3 = su[(lb+3)*129 + ka];
                u64 p01, p23;
                PKP(p01, a0, a1); PKP(p23, a2, a3);
                float4 wv = *(const float4*)&U[kk*64 + (ng << 2)];
                u64 b0, b1, b2, b3;
                PK1(b0, wv.x); PK1(b1, wv.y); PK1(b2, wv.z); PK1(b3, wv.w);
                FMA2(acc[0][0], p01, b0, acc[0][0]); FMA2(acc[0][1], p01, b1, acc[0][1]);
                FMA2(acc[0][2], p01, b2, acc[0][2]); FMA2(acc[0][3], p01, b3, acc[0][3]);
                FMA2(acc[1][0], p23, b0, acc[1][0]); FMA2(acc[1][1], p23, b1, acc[1][1]);
                FMA2(acc[1][2], p23, b2, acc[1][2]); FMA2(acc[1][3], p23, b3, acc[1][3]);
            }
            __syncthreads();
        }
        if (ng < 9) {
#pragma unroll
            for (int p = 0; p < 2; p++) {
                float lo[4], hi[4];
#pragma unroll
                for (int cc = 0; cc < 4; cc++) UNPK2(lo[cc], hi[cc], acc[p][cc]);
#pragma unroll
                for (int cc = 0; cc < 4; cc++) {
                    xds[(lb + 2*p)*36 + (ng << 2) + cc]     = lo[cc];
                    xds[(lb + 2*p + 1)*36 + (ng << 2) + cc] = hi[cc];
                }
            }
        }
    }
    __syncthreads();

    // ===== Phase C: scan pass1 =====
    int d = tid;
    float4 w = *(const float4*)&dtw[d*4];
    float bias = __ldg(&dtb[d]);
    float Dd = __ldg(&Dp[d]);
    int structured = *flagp;
    float A0 = Ap[d*NST];
    float* o = hp + (((long)b*NCH + c)*DIN + d)*32;
    float S = 0.f;
    if (structured) {
        u64 h2[8];
#pragma unroll
        for (int p = 0; p < 8; p++) h2[p] = 0ULL;
        for (int t = 0; t < TCH; t++) {
            const float* xt = xds + t*36;
            float dt = fmaf(xt[0], w.x, fmaf(xt[1], w.y, fmaf(xt[2], w.z, fmaf(xt[3], w.w, bias))));
            dt = softplusf(dt);
            S += dt;
            float du = dt * su[t*129 + d];
            float r = __expf(dt * A0);
            float r2 = r * r;
            u64 a2, rr2, du2;
            PKP(a2, r, r2); PK1(rr2, r2); PK1(du2, du);
#pragma unroll
            for (int p = 0; p < 8; p++) {
                u64 bp = *(const u64*)&xt[4 + 2*p];
                u64 m;
                MUL2(m, du2, bp);
                FMA2(h2[p], a2, h2[p], m);
                if (p < 7) MUL2(a2, a2, rr2);
            }
        }
#pragma unroll
        for (int p = 0; p < 8; p++) *(u64*)&o[2*p] = h2[p];
        float q = __expf(S * A0), qc = q;
#pragma unroll
        for (int n = 0; n < NST; n++) { o[16 + n] = qc; qc *= q; }
    } else {
        float Ar[NST], h[NST];
#pragma unroll
        for (int n = 0; n < NST; n++) { Ar[n] = Ap[d*NST + n]; h[n] = 0.f; }
        for (int t = 0; t < TCH; t++) {
            const float* xt = xds + t*36;
            float dt = fmaf(xt[0], w.x, fmaf(xt[1], w.y, fmaf(xt[2], w.z, fmaf(xt[3], w.w, bias))));
            dt = softplusf(dt);
            S += dt;
            float du = dt * su[t*129 + d];
#pragma unroll
            for (int n = 0; n < NST; n++) {
                float a = __expf(dt * Ar[n]);
                h[n] = fmaf(a, h[n], du * xt[4 + n]);
            }
        }
#pragma unroll
        for (int n = 0; n < NST; n++) { o[n] = h[n]; o[16 + n] = __expf(S * Ar[n]); }
    }

    gridbar(tid);

    // ===== segmented chunk combine (all 65536 threads) =====
    {
        int g = (b*NCH + c)*128 + d;
        int s = g >> 3, sg = g & 7;
        int b2 = s >> 11;
        int dn = s & 2047;
        int off = ((dn >> 4) << 5) + (dn & 15);
        long base = (long)b2 * NCH * (DIN*32) + off + (long)sg * 16 * (DIN*32);
        float he[16], pp[16];
        float H = 0.f, P = 1.f;
#pragma unroll
        for (int j = 0; j < 16; j++) {
            he[j] = hp[base + (long)j*(DIN*32)];
            pp[j] = hp[base + (long)j*(DIN*32) + 16];
        }
#pragma unroll
        for (int j = 0; j < 16; j++) {
            H = fmaf(pp[j], H, he[j]);
            P *= pp[j];
        }
#pragma unroll
        for (int k = 1; k < 8; k <<= 1) {
            float Hu = __shfl_up_sync(0xffffffffu, H, k, 8);
            float Pu = __shfl_up_sync(0xffffffffu, P, k, 8);
            if (sg >= k) { H = fmaf(P, Hu, H); P *= Pu; }
        }
        float Hx = __shfl_up_sync(0xffffffffu, H, 1, 8);
        if (sg == 0) Hx = 0.f;
        float Hc = Hx;
#pragma unroll
        for (int j = 0; j < 16; j++) {
            hp[base + (long)j*(DIN*32)] = Hc;
            Hc = fmaf(pp[j], Hc, he[j]);
        }
    }

    gridbar(tid);

    // ===== Phase D: scan pass3 (dt recomputed) =====
    if (structured) {
        u64 h2[8];
#pragma unroll
        for (int p = 0; p < 8; p++) h2[p] = *(const u64*)&o[2*p];
        for (int t = 0; t < TCH; t++) {
            const float* xt = xds + t*36;
            float dt = fmaf(xt[0], w.x, fmaf(xt[1], w.y, fmaf(xt[2], w.z, fmaf(xt[3], w.w, bias))));
            dt = softplusf(dt);
            float ut = su[t*129 + d];
            float du = dt * ut;
            float r = __expf(dt * A0);
            float r2 = r * r;
            u64 a2, rr2, du2, y2 = 0ULL;
            PKP(a2, r, r2); PK1(rr2, r2); PK1(du2, du);
#pragma unroll
            for (int p = 0; p < 8; p++) {
                u64 bp = *(const u64*)&xt[4 + 2*p];
                u64 cp = *(const u64*)&xt[20 + 2*p];
                u64 m;
                MUL2(m, du2, bp);
                FMA2(h2[p], a2, h2[p], m);
                FMA2(y2, h2[p], cp, y2);
                if (p < 7) MUL2(a2, a2, rr2);
            }
            float ylo, yhi;
            UNPK2(ylo, yhi, y2);
            float rt = xr[(lc + t)*256 + 128 + d];
            ys[t*129 + d] = fmaf(ut, Dd, ylo + yhi) * siluf(rt);
        }
    } else {
        float Ar[NST], h[NST];
#pragma unroll
        for (int n = 0; n < NST; n++) { Ar[n] = Ap[d*NST + n]; h[n] = o[n]; }
        for (int t = 0; t < TCH; t++) {
            const float* xt = xds + t*36;
            float dt = fmaf(xt[0], w.x, fmaf(xt[1], w.y, fmaf(xt[2], w.z, fmaf(xt[3], w.w, bias))));
            dt = softplusf(dt);
            float ut = su[t*129 + d];
            float du = dt * ut;
            float y = 0.f;
#pragma unroll
            for (int n = 0; n < NST; n++) {
                float a = __expf(dt * Ar[n]);
                h[n] = fmaf(a, h[n], du * xt[4 + n]);
                y = fmaf(h[n], xt[20 + n], y);
            }
            float rt = xr[(lc + t)*256 + 128 + d];
            ys[t*129 + d] = fmaf(ut, Dd, y) * siluf(rt);
        }
    }
    __syncthreads();

    // ===== Phase E: out_proj GEMM (32l x 64n x K=128) from ys + LayerNorm =====
    {
        int lj = tid >> 4, ng = tid & 15;
        int lb = lj << 2;
        u64 acc[2][4];
#pragma unroll
        for (int p = 0; p < 2; p++)
#pragma unroll
            for (int cc = 0; cc < 4; cc++) acc[p][cc] = 0ULL;
        for (int kt = 0; kt < 4; kt++) {
            for (int e = tid; e < 512; e += 128) {
                int k = e >> 4, nq = e & 15;
                *(float4*)&U[k*64 + (nq << 2)] =
                    *(const float4*)&wot[(kt*32 + k)*64 + (nq << 2)];
            }
            __syncthreads();
#pragma unroll 8
            for (int kk = 0; kk < 32; kk++) {
                int ka = kt*32 + kk;
                float a0 = ys[(lb+0)*129 + ka], a1 = ys[(lb+1)*129 + ka];
                float a2 = ys[(lb+2)*129 + ka], a3 = ys[(lb+3)*129 + ka];
                u64 p01, p23;
                PKP(p01, a0, a1); PKP(p23, a2, a3);
                float4 wv = *(const float4*)&U[kk*64 + (ng << 2)];
                u64 b0, b1, b2, b3;
                PK1(b0, wv.x); PK1(b1, wv.y); PK1(b2, wv.z); PK1(b3, wv.w);
                FMA2(acc[0][0], p01, b0, acc[0][0]); FMA2(acc[0][1], p01, b1, acc[0][1]);
                FMA2(acc[0][2], p01, b2, acc[0][2]); FMA2(acc[0][3], p01, b3, acc[0][3]);
                FMA2(acc[1][0], p23, b0, acc[1][0]); FMA2(acc[1][1], p23, b1, acc[1][1]);
                FMA2(acc[1][2], p23, b2, acc[1][2]); FMA2(acc[1][3], p23, b3, acc[1][3]);
            }
            __syncthreads();
        }
        // stage into st = U [32 l][65]
        float* st = U;
#pragma unroll
        for (int p = 0; p < 2; p++) {
#pragma unroll
            for (int cc = 0; cc < 4; cc++) {
                float lo, hi;
                UNPK2(lo, hi, acc[p][cc]);
                st[(lb + 2*p)*65 + (ng << 2) + cc]     = lo;
                st[(lb + 2*p + 1)*65 + (ng << 2) + cc] = hi;
            }
        }
        __syncthreads();
        // LayerNorm: 4 threads per row (32 rows), 16 cols each
        int row = tid >> 2, q = tid & 3;
        float v[16], s = 0.f, s2 = 0.f;
#pragma unroll
        for (int j = 0; j < 16; j++) {
            float x = st[row*65 + q*16 + j];
            v[j] = x; s += x; s2 += x * x;
        }
        s  += __shfl_xor_sync(0xffffffffu, s, 1);
        s2 += __shfl_xor_sync(0xffffffffu, s2, 1);
        s  += __shfl_xor_sync(0xffffffffu, s, 2);
        s2 += __shfl_xor_sync(0xffffffffu, s2, 2);
        float mean = s * 0.015625f;
        float var  = s2 * 0.015625f - mean * mean;
        float rstd = rsqrtf(var + 1e-5f);
#pragma unroll
        for (int j = 0; j < 16; j++) {
            int n = q*16 + j;
            st[row*65 + n] = (v[j] - mean) * rstd * __ldg(&lng[n]) + __ldg(&lnb[n]);
        }
        __syncthreads();
        // transposed coalesced write: gout[b][n][lcl + l]
        for (int e = tid; e < 512; e += 128) {
            int n = e >> 3, l4 = e & 7;
            int l = l4 << 2;
            float4 o4 = make_float4(st[l*65 + n],       st[(l+1)*65 + n],
                                    st[(l+2)*65 + n],   st[(l+3)*65 + n]);
            *(float4*)&gout[((long)b*64 + n)*SEQL + lcl + l] = o4;
        }
    }
}

// ---------------- host ----------------
extern "C" void kernel_launch(void* const* d_in, const int* in_sizes, int n_in,
                              void* d_out, int out_size) {
    const float* x1 = (const float*)d_in[0];
    float* out = (float*)d_out;

    float *xr, *hp, *xmid, *w1t, *wxt, *wot, *Ab;
    int* Afl;
    cudaGetSymbolAddress((void**)&xr,   g_xr);
    cudaGetSymbolAddress((void**)&hp,   g_hp);
    cudaGetSymbolAddress((void**)&xmid, g_xmid);
    cudaGetSymbolAddress((void**)&w1t,  g_w1t);
    cudaGetSymbolAddress((void**)&wxt,  g_wxt);
    cudaGetSymbolAddress((void**)&wot,  g_wot);
    cudaGetSymbolAddress((void**)&Ab,   g_Ab);
    cudaGetSymbolAddress((void**)&Afl,  g_Afl);

    prep_k<<<dim3(136, 2), 256>>>(
        (const float*)d_in[1], (const float*)d_in[4], (const float*)d_in[9], (const float*)d_in[7],
        (const float*)d_in[10], (const float*)d_in[13], (const float*)d_in[18], (const float*)d_in[16],
        w1t, wxt, wot, Ab);
    chkA_k<<<2, 256>>>(Ab, Ab + 2048, Afl);

    const int GSM = 33280;
    const int MSM = (2*32*129 + 32*36 + 4480) * 4;   // 55552 B
    cudaFuncSetAttribute(mega_k, cudaFuncAttributeMaxDynamicSharedMemorySize, MSM);

    for (int m = 0; m < 2; m++) {
        const float* cw  = (const float*)d_in[1 + 9*m + 1];
        const float* cb  = (const float*)d_in[1 + 9*m + 2];
        const float* dtw = (const float*)d_in[1 + 9*m + 4];
        const float* dtb = (const float*)d_in[1 + 9*m + 5];
        const float* Dp  = (const float*)d_in[1 + 9*m + 7];
        const float* lng = (const float*)d_in[19 + 2*m];
        const float* lnb = (const float*)d_in[20 + 2*m];
        const float* Abm = Ab + m*2048;
        const int*   flm = Afl + m;

        const float* Xin = (m == 0) ? x1 : xmid;      // k-major [b][64][4096]
        float* gout = (m == 0) ? xmid : out;          // k-major [b][64][4096]

        // in_proj: K=64, N=256 -> xr row-major [l][256]
        gemm_k<<<dim3(SEQL/64, 4, BATCH), 256, GSM>>>(
            Xin, w1t + m*16384, xr, 64, 256, 256);
        // MEGA: conv + x_proj + scan + out_proj + LN, one persistent launch
        mega_k<<<dim3(NCH, BATCH), DIN, MSM>>>(
            xr, cw, cb, wxt + m*8192, Abm, dtw, dtb, Dp,
            wot + m*8192, lng, lnb, hp, gout, flm);
    }
}

// round 15
// speedup vs baseline: 1.0609x; 1.0021x over previous
#include <cuda_runtime.h>

#define BATCH 4
#define SEQL  4096
#define DIN   128
#define NST   16
#define TCH   32
#define NCH   128   /* SEQL / TCH */
#define SP    132   /* su/ys pitch: 132*4=528B, 16B-aligned rows */

typedef unsigned long long u64;

#define FMA2(d, a, b, c) asm("fma.rn.f32x2 %0, %1, %2, %3;" : "=l"(d) : "l"(a), "l"(b), "l"(c))
#define MUL2(d, a, b)    asm("mul.rn.f32x2 %0, %1, %2;" : "=l"(d) : "l"(a), "l"(b))
#define UNPK2(x, y, in)  asm("mov.b64 {%0, %1}, %2;" : "=f"(x), "=f"(y) : "l"(in))
#define PK1(d, x)        asm("mov.b64 %0, {%1, %1};" : "=l"(d) : "f"(x))
#define PKP(d, x, y)     asm("mov.b64 %0, {%1, %2};" : "=l"(d) : "f"(x), "f"(y))

#define CPA16(dst, src)  asm volatile("cp.async.cg.shared.global [%0], [%1], 16;" :: "r"(dst), "l"(src) : "memory")
#define CPCOM()          asm volatile("cp.async.commit_group;" ::: "memory")
#define CPWAIT1()        asm volatile("cp.async.wait_group 1;" ::: "memory")
#define CPWAIT0()        asm volatile("cp.async.wait_group 0;" ::: "memory")

// ---------------- scratch (device globals; no allocation) ----------------
__device__ float g_xr  [BATCH*SEQL*256];   // in_proj output (u | res), row-major [l][256]
__device__ float g_hp  [BATCH*NCH*DIN*32]; // per-chunk [h_end(16)|P(16)] -> H_init
__device__ float g_xmid[BATCH*64*SEQL];    // between mambas, k-major [b][c][l]
__device__ float g_w1t [2][64*256];        // in_proj W transposed [k][n]
__device__ float g_wxt [2][128*64];        // x_proj W transposed, zero-padded to 64
__device__ float g_wot [2][128*64];        // out_proj W transposed
__device__ float g_Ab  [2][DIN*NST];       // A = -exp(Alog)
__device__ int   g_Afl [2];                // 1 if A[d][n] == (n+1)*A[d][0]
__device__ unsigned g_ctr = 0;             // grid-barrier ticket counter (monotonic)

__device__ __forceinline__ float softplusf(float x) {
    return x > 15.f ? x : __logf(1.f + __expf(x));
}
__device__ __forceinline__ float siluf(float x) {
    return x / (1.f + __expf(-x));
}

// ---------------- prep: both mambas in one launch ----------------
__global__ void prep_k(const float* __restrict__ iw0, const float* __restrict__ xp0,
                       const float* __restrict__ ow0, const float* __restrict__ al0,
                       const float* __restrict__ iw1, const float* __restrict__ xp1,
                       const float* __restrict__ ow1, const float* __restrict__ al1,
                       float* __restrict__ w1t, float* __restrict__ wxt,
                       float* __restrict__ wot, float* __restrict__ Ab) {
    int m = blockIdx.y;
    const float* in_w  = m ? iw1 : iw0;
    const float* xproj = m ? xp1 : xp0;
    const float* out_w = m ? ow1 : ow0;
    const float* Alog  = m ? al1 : al0;
    float* w1 = w1t + m*16384;
    float* wx = wxt + m*8192;
    float* wo = wot + m*8192;
    float* Am = Ab  + m*2048;
    int idx = blockIdx.x * 256 + threadIdx.x;
    if (idx < 16384) { int k = idx >> 8, n = idx & 255; w1[idx] = in_w[n*64 + k]; return; }
    idx -= 16384;
    if (idx < 8192)  { int k = idx >> 6, n = idx & 63; wx[idx] = (n < 36) ? xproj[n*128 + k] : 0.f; return; }
    idx -= 8192;
    if (idx < 8192)  { int k = idx >> 6, n = idx & 63; wo[idx] = out_w[n*128 + k]; return; }
    idx -= 8192;
    if (idx < 2048)  Am[idx] = -expf(Alog[idx]);
}

__global__ void chkA_k(const float* __restrict__ A0, const float* __restrict__ A1,
                       int* __restrict__ fl) {
    const float* A = blockIdx.x ? A1 : A0;
    __shared__ int ok;
    if (threadIdx.x == 0) ok = 1;
    __syncthreads();
    int bad = 0;
    for (int e = threadIdx.x; e < DIN*NST; e += 256) {
        int d = e >> 4, n = e & 15;
        float expv = (float)(n + 1) * A[d*16];
        if (fabsf(A[e] - expv) > 1e-5f * fabsf(expv) + 1e-20f) bad = 1;
    }
    if (bad) atomicAnd(&ok, 0);
    __syncthreads();
    if (threadIdx.x == 0) fl[blockIdx.x] = ok;
}

// ---------------- pipelined GEMM (in_proj only): X k-major; tile 64L x 64N ----------------
__global__ __launch_bounds__(256) void gemm_k(
    const float* __restrict__ X, const float* __restrict__ Wt, float* __restrict__ Out,
    int K, int Nld, int Nout)
{
    extern __shared__ float sm[];
    int tid = threadIdx.x;
    int l0 = blockIdx.x << 6;
    int n0 = blockIdx.y << 6;
    int b  = blockIdx.z;
    const float* Xb = X + (long)b * K * SEQL;
    int lj = tid >> 4, ng = tid & 15;
    int lb = lj << 2;
    unsigned smb = (unsigned)__cvta_generic_to_shared(sm);
    int ntiles = K >> 5;

    {
#pragma unroll
        for (int i = 0; i < 2; i++) {
            int e = tid + (i << 8);
            int k = e >> 4, lq = e & 15;
            CPA16(smb + (((k << 6) + (lq << 2)) << 2),
                  Xb + (long)k * SEQL + l0 + (lq << 2));
        }
#pragma unroll
        for (int i = 0; i < 2; i++) {
            int e = tid + (i << 8);
            int k = e >> 4, nq = e & 15;
            CPA16(smb + 16384u + (((k << 6) + (nq << 2)) << 2),
                  Wt + (long)k * Nld + n0 + (nq << 2));
        }
        CPCOM();
    }

    u64 acc[2][4];
#pragma unroll
    for (int p = 0; p < 2; p++)
#pragma unroll
        for (int c = 0; c < 4; c++) acc[p][c] = 0ULL;

    for (int tt = 0; tt < ntiles; tt++) {
        int s = tt & 1;
        if (tt + 1 < ntiles) {
            int kofs = (tt + 1) << 5;
            int s2 = s ^ 1;
#pragma unroll
            for (int i = 0; i < 2; i++) {
                int e = tid + (i << 8);
                int k = e >> 4, lq = e & 15;
                CPA16(smb + (((s2 << 11) + (k << 6) + (lq << 2)) << 2),
                      Xb + (long)(kofs + k) * SEQL + l0 + (lq << 2));
            }
#pragma unroll
            for (int i = 0; i < 2; i++) {
                int e = tid + (i << 8);
                int k = e >> 4, nq = e & 15;
                CPA16(smb + 16384u + (((s2 << 11) + (k << 6) + (nq << 2)) << 2),
                      Wt + (long)(kofs + k) * Nld + n0 + (nq << 2));
            }
            CPCOM();
            CPWAIT1();
        } else {
            CPWAIT0();
        }
        __syncthreads();
        const float* xs = sm + (s << 11);
        const float* ws = sm + 4096 + (s << 11);
#pragma unroll 8
        for (int kk = 0; kk < 32; kk++) {
            ulonglong2 av = *(const ulonglong2*)&xs[(kk << 6) + lb];
            float4 wv = *(const float4*)&ws[(kk << 6) + (ng << 2)];
            u64 b0, b1, b2, b3;
            PK1(b0, wv.x); PK1(b1, wv.y); PK1(b2, wv.z); PK1(b3, wv.w);
            FMA2(acc[0][0], av.x, b0, acc[0][0]); FMA2(acc[0][1], av.x, b1, acc[0][1]);
            FMA2(acc[0][2], av.x, b2, acc[0][2]); FMA2(acc[0][3], av.x, b3, acc[0][3]);
            FMA2(acc[1][0], av.y, b0, acc[1][0]); FMA2(acc[1][1], av.y, b1, acc[1][1]);
            FMA2(acc[1][2], av.y, b2, acc[1][2]); FMA2(acc[1][3], av.y, b3, acc[1][3]);
        }
        __syncthreads();
    }

#pragma unroll
    for (int p = 0; p < 2; p++) {
        float lo[4], hi[4];
#pragma unroll
        for (int c = 0; c < 4; c++) UNPK2(lo[c], hi[c], acc[p][c]);
        long r0 = ((long)b*SEQL + l0 + lb + 2*p) * Nout + n0 + (ng << 2);
        *(float4*)&Out[r0]        = make_float4(lo[0], lo[1], lo[2], lo[3]);
        *(float4*)&Out[r0 + Nout] = make_float4(hi[0], hi[1], hi[2], hi[3]);
    }
}

// ---------------- grid barrier (all 512 blocks resident by construction) ----------------
__device__ __forceinline__ void gridbar(int tid) {
    __syncthreads();
    if (tid == 0) {
        __threadfence();
        unsigned t = atomicAdd(&g_ctr, 1u);
        unsigned target = (t & ~511u) + 512u;
        volatile unsigned* p = &g_ctr;
        while ((int)(*p - target) < 0) __nanosleep(64);
    }
    __syncthreads();
    __threadfence();
}

// ---------------- MEGA: conv+silu + x_proj + scan + out_proj + LayerNorm ----------------
// grid (NCH, BATCH) = 512 blocks x 128 thr; smem 56.3KB -> 4 blocks/SM, all resident.
// smem floats: su[32*SP] | ys[32*SP] | xds[32*36] | U[4480]
//   U = union of: xh halo (35*128), W k-tile (32*64), r/dt store (32*128), LN staging (32*65)
//   ys doubles as du store between precompute and pass3 (same-thread read-then-write).
__global__ __launch_bounds__(128, 4) void mega_k(
    const float* __restrict__ xr,
    const float* __restrict__ cw,  const float* __restrict__ cb,
    const float* __restrict__ wxt,
    const float* __restrict__ Ap,
    const float* __restrict__ dtw, const float* __restrict__ dtb,
    const float* __restrict__ Dp,
    const float* __restrict__ wot,
    const float* __restrict__ lng, const float* __restrict__ lnb,
    float* __restrict__ hp,
    float* __restrict__ gout,
    const int* __restrict__ flagp)
{
    extern __shared__ float sm[];
    float* su  = sm;                // [32 t][SP]
    float* ys  = sm + 32*SP;        // [32 t][SP]
    float* xds = sm + 2*32*SP;      // [32 t][36]
    float* U   = xds + 32*36;       // union region (4480 floats)

    int tid = threadIdx.x;
    int c = blockIdx.x, b = blockIdx.y;
    int lcl = c*TCH;
    long lc = (long)b*SEQL + lcl;

    // ===== Phase A: conv + silu =====
    for (int e = tid; e < 35*32; e += 128) {
        int row = e >> 5, d4 = e & 31;
        int lg = lcl - 3 + row;
        float4 v = (lg >= 0) ? *(const float4*)&xr[((long)b*SEQL + lg)*256 + (d4 << 2)]
                             : make_float4(0.f, 0.f, 0.f, 0.f);
        *(float4*)&U[row*128 + (d4 << 2)] = v;
    }
    __syncthreads();
    {
        int d = tid;
        float4 w = *(const float4*)&cw[d*4];
        float bias = __ldg(&cb[d]);
#pragma unroll 8
        for (int l = 0; l < 32; l++) {
            float s = fmaf(w.x, U[l*128 + d], fmaf(w.y, U[(l+1)*128 + d],
                      fmaf(w.z, U[(l+2)*128 + d], fmaf(w.w, U[(l+3)*128 + d], bias))));
            su[l*SP + d] = siluf(s);
        }
    }
    __syncthreads();

    // ===== Phase B: x_proj GEMM (32l x 64n x K=128) from su, LDS.128 quads =====
    {
        int lj = tid >> 4, ng = tid & 15;
        int lb = lj << 2;
        u64 acc[2][4];
#pragma unroll
        for (int p = 0; p < 2; p++)
#pragma unroll
            for (int cc = 0; cc < 4; cc++) acc[p][cc] = 0ULL;
        for (int kt = 0; kt < 4; kt++) {
            for (int e = tid; e < 512; e += 128) {
                int k = e >> 4, nq = e & 15;
                *(float4*)&U[k*64 + (nq << 2)] =
                    *(const float4*)&wxt[(kt*32 + k)*64 + (nq << 2)];
            }
            __syncthreads();
#pragma unroll
            for (int kq = 0; kq < 8; kq++) {
                int ka = kt*32 + (kq << 2);
                float4 a0 = *(const float4*)&su[(lb+0)*SP + ka];
                float4 a1 = *(const float4*)&su[(lb+1)*SP + ka];
                float4 a2 = *(const float4*)&su[(lb+2)*SP + ka];
                float4 a3 = *(const float4*)&su[(lb+3)*SP + ka];
                float A0a[4] = {a0.x, a0.y, a0.z, a0.w};
                float A1a[4] = {a1.x, a1.y, a1.z, a1.w};
                float A2a[4] = {a2.x, a2.y, a2.z, a2.w};
                float A3a[4] = {a3.x, a3.y, a3.z, a3.w};
#pragma unroll
                for (int j = 0; j < 4; j++) {
                    float4 wv = *(const float4*)&U[((kq << 2) + j)*64 + (ng << 2)];
                    u64 p01, p23, b0, b1, b2, b3;
                    PKP(p01, A0a[j], A1a[j]); PKP(p23, A2a[j], A3a[j]);
                    PK1(b0, wv.x); PK1(b1, wv.y); PK1(b2, wv.z); PK1(b3, wv.w);
                    FMA2(acc[0][0], p01, b0, acc[0][0]); FMA2(acc[0][1], p01, b1, acc[0][1]);
                    FMA2(acc[0][2], p01, b2, acc[0][2]); FMA2(acc[0][3], p01, b3, acc[0][3]);
                    FMA2(acc[1][0], p23, b0, acc[1][0]); FMA2(acc[1][1], p23, b1, acc[1][1]);
                    FMA2(acc[1][2], p23, b2, acc[1][2]); FMA2(acc[1][3], p23, b3, acc[1][3]);
                }
            }
            __syncthreads();
        }
        if (ng < 9) {
#pragma unroll
            for (int p = 0; p < 2; p++) {
                float lo[4], hi[4];
#pragma unroll
                for (int cc = 0; cc < 4; cc++) UNPK2(lo[cc], hi[cc], acc[p][cc]);
#pragma unroll
                for (int cc = 0; cc < 4; cc++) {
                    xds[(lb + 2*p)*36 + (ng << 2) + cc]     = lo[cc];
                    xds[(lb + 2*p + 1)*36 + (ng << 2) + cc] = hi[cc];
                }
            }
        }
    }
    __syncthreads();

    // ===== Precompute: dt -> (r|dt) in U, du in ys; S accumulated =====
    int d = tid;
    float4 w = *(const float4*)&dtw[d*4];
    float bias = __ldg(&dtb[d]);
    float Dd = __ldg(&Dp[d]);
    int structured = *flagp;
    float A0 = Ap[d*NST];
    float* o = hp + (((long)b*NCH + c)*DIN + d)*32;
    float S = 0.f;
#pragma unroll 8
    for (int t = 0; t < TCH; t++) {
        const float* xt = xds + t*36;
        float dt = fmaf(xt[0], w.x, fmaf(xt[1], w.y, fmaf(xt[2], w.z, fmaf(xt[3], w.w, bias))));
        dt = softplusf(dt);
        S += dt;
        ys[t*SP + d] = dt * su[t*SP + d];                      // du
        U[t*128 + d] = structured ? __expf(dt * A0) : dt;      // r or dt
    }
    // (no sync needed: pass1/pass3 read only this thread's U/ys columns)

    // ===== pass 1: local scan from h=0 (pure FMA2; log-depth powers) =====
    if (structured) {
        u64 h2[8];
#pragma unroll
        for (int p = 0; p < 8; p++) h2[p] = 0ULL;
#pragma unroll 4
        for (int t = 0; t < TCH; t++) {
            const float* xt = xds + t*36;
            float r = U[t*128 + d];
            float r2 = r*r, r4 = r2*r2, r8 = r4*r4;
            u64 du2, q0, v2, v4, v8, q1, q2, q3, q4, q5, q6, q7;
            PK1(du2, ys[t*SP + d]);
            PKP(q0, r, r2);
            PK1(v2, r2); PK1(v4, r4); PK1(v8, r8);
            MUL2(q1, q0, v2); MUL2(q2, q0, v4); MUL2(q3, q1, v4);
            MUL2(q4, q0, v8); MUL2(q5, q1, v8); MUL2(q6, q2, v8); MUL2(q7, q3, v8);
            u64 qs[8] = {q0, q1, q2, q3, q4, q5, q6, q7};
#pragma unroll
            for (int p = 0; p < 8; p++) {
                u64 bp = *(const u64*)&xt[4 + 2*p];
                u64 m;
                MUL2(m, du2, bp);
                FMA2(h2[p], qs[p], h2[p], m);
            }
        }
#pragma unroll
        for (int p = 0; p < 8; p++) *(u64*)&o[2*p] = h2[p];
        float q = __expf(S * A0), qc = q;
#pragma unroll
        for (int n = 0; n < NST; n++) { o[16 + n] = qc; qc *= q; }
    } else {
        float Ar[NST], h[NST];
#pragma unroll
        for (int n = 0; n < NST; n++) { Ar[n] = Ap[d*NST + n]; h[n] = 0.f; }
        for (int t = 0; t < TCH; t++) {
            const float* xt = xds + t*36;
            float dt = U[t*128 + d];
            float du = ys[t*SP + d];
#pragma unroll
            for (int n = 0; n < NST; n++) {
                float a = __expf(dt * Ar[n]);
                h[n] = fmaf(a, h[n], du * xt[4 + n]);
            }
        }
#pragma unroll
        for (int n = 0; n < NST; n++) { o[n] = h[n]; o[16 + n] = __expf(S * Ar[n]); }
    }

    gridbar(tid);

    // ===== segmented chunk combine (all 65536 threads) =====
    {
        int g = (b*NCH + c)*128 + d;
        int s = g >> 3, sg = g & 7;
        int b2 = s >> 11;
        int dn = s & 2047;
        int off = ((dn >> 4) << 5) + (dn & 15);
        long base = (long)b2 * NCH * (DIN*32) + off + (long)sg * 16 * (DIN*32);
        float he[16], pp[16];
        float H = 0.f, P = 1.f;
#pragma unroll
        for (int j = 0; j < 16; j++) {
            he[j] = hp[base + (long)j*(DIN*32)];
            pp[j] = hp[base + (long)j*(DIN*32) + 16];
        }
#pragma unroll
        for (int j = 0; j < 16; j++) {
            H = fmaf(pp[j], H, he[j]);
            P *= pp[j];
        }
#pragma unroll
        for (int k = 1; k < 8; k <<= 1) {
            float Hu = __shfl_up_sync(0xffffffffu, H, k, 8);
            float Pu = __shfl_up_sync(0xffffffffu, P, k, 8);
            if (sg >= k) { H = fmaf(P, Hu, H); P *= Pu; }
        }
        float Hx = __shfl_up_sync(0xffffffffu, H, 1, 8);
        if (sg == 0) Hx = 0.f;
        float Hc = Hx;
#pragma unroll
        for (int j = 0; j < 16; j++) {
            hp[base + (long)j*(DIN*32)] = Hc;
            Hc = fmaf(pp[j], Hc, he[j]);
        }
    }

    gridbar(tid);

    // ===== pass 3: replay from H_init; y = C.h + u*D; gate by silu(res) =====
    if (structured) {
        u64 h2[8];
#pragma unroll
        for (int p = 0; p < 8; p++) h2[p] = *(const u64*)&o[2*p];
#pragma unroll 4
        for (int t = 0; t < TCH; t++) {
            const float* xt = xds + t*36;
            float r = U[t*128 + d];
            float du = ys[t*SP + d];
            float ut = su[t*SP + d];
            float r2 = r*r, r4 = r2*r2, r8 = r4*r4;
            u64 du2, q0, v2, v4, v8, q1, q2, q3, q4, q5, q6, q7, y2 = 0ULL;
            PK1(du2, du);
            PKP(q0, r, r2);
            PK1(v2, r2); PK1(v4, r4); PK1(v8, r8);
            MUL2(q1, q0, v2); MUL2(q2, q0, v4); MUL2(q3, q1, v4);
            MUL2(q4, q0, v8); MUL2(q5, q1, v8); MUL2(q6, q2, v8); MUL2(q7, q3, v8);
            u64 qs[8] = {q0, q1, q2, q3, q4, q5, q6, q7};
#pragma unroll
            for (int p = 0; p < 8; p++) {
                u64 bp = *(const u64*)&xt[4 + 2*p];
                u64 cp = *(const u64*)&xt[20 + 2*p];
                u64 m;
                MUL2(m, du2, bp);
                FMA2(h2[p], qs[p], h2[p], m);
                FMA2(y2, h2[p], cp, y2);
            }
            float ylo, yhi;
            UNPK2(ylo, yhi, y2);
            float rt = xr[(lc + t)*256 + 128 + d];
            ys[t*SP + d] = fmaf(ut, Dd, ylo + yhi) * siluf(rt);
        }
    } else {
        float Ar[NST], h[NST];
#pragma unroll
        for (int n = 0; n < NST; n++) { Ar[n] = Ap[d*NST + n]; h[n] = o[n]; }
        for (int t = 0; t < TCH; t++) {
            const float* xt = xds + t*36;
            float dt = U[t*128 + d];
            float du = ys[t*SP + d];
            float ut = su[t*SP + d];
            float y = 0.f;
#pragma unroll
            for (int n = 0; n < NST; n++) {
                float a = __expf(dt * Ar[n]);
                h[n] = fmaf(a, h[n], du * xt[4 + n]);
                y = fmaf(h[n], xt[20 + n], y);
            }
            float rt = xr[(lc + t)*256 + 128 + d];
            ys[t*SP + d] = fmaf(ut, Dd, y) * siluf(rt);
        }
    }
    __syncthreads();

    // ===== Phase E: out_proj GEMM (32l x 64n x K=128) from ys + LayerNorm =====
    {
        int lj = tid >> 4, ng = tid & 15;
        int lb = lj << 2;
        u64 acc[2][4];
#pragma unroll
        for (int p = 0; p < 2; p++)
#pragma unroll
            for (int cc = 0; cc < 4; cc++) acc[p][cc] = 0ULL;
        for (int kt = 0; kt < 4; kt++) {
            for (int e = tid; e < 512; e += 128) {
                int k = e >> 4, nq = e & 15;
                *(float4*)&U[k*64 + (nq << 2)] =
                    *(const float4*)&wot[(kt*32 + k)*64 + (nq << 2)];
            }
            __syncthreads();
#pragma unroll
            for (int kq = 0; kq < 8; kq++) {
                int ka = kt*32 + (kq << 2);
                float4 a0 = *(const float4*)&ys[(lb+0)*SP + ka];
                float4 a1 = *(const float4*)&ys[(lb+1)*SP + ka];
                float4 a2 = *(const float4*)&ys[(lb+2)*SP + ka];
                float4 a3 = *(const float4*)&ys[(lb+3)*SP + ka];
                float A0a[4] = {a0.x, a0.y, a0.z, a0.w};
                float A1a[4] = {a1.x, a1.y, a1.z, a1.w};
                float A2a[4] = {a2.x, a2.y, a2.z, a2.w};
                float A3a[4] = {a3.x, a3.y, a3.z, a3.w};
#pragma unroll
                for (int j = 0; j < 4; j++) {
                    float4 wv = *(const float4*)&U[((kq << 2) + j)*64 + (ng << 2)];
                    u64 p01, p23, b0, b1, b2, b3;
                    PKP(p01, A0a[j], A1a[j]); PKP(p23, A2a[j], A3a[j]);
                    PK1(b0, wv.x); PK1(b1, wv.y); PK1(b2, wv.z); PK1(b3, wv.w);
                    FMA2(acc[0][0], p01, b0, acc[0][0]); FMA2(acc[0][1], p01, b1, acc[0][1]);
                    FMA2(acc[0][2], p01, b2, acc[0][2]); FMA2(acc[0][3], p01, b3, acc[0][3]);
                    FMA2(acc[1][0], p23, b0, acc[1][0]); FMA2(acc[1][1], p23, b1, acc[1][1]);
                    FMA2(acc[1][2], p23, b2, acc[1][2]); FMA2(acc[1][3], p23, b3, acc[1][3]);
                }
            }
            __syncthreads();
        }
        // stage into st = U [32 l][65]
        float* st = U;
#pragma unroll
        for (int p = 0; p < 2; p++) {
#pragma unroll
            for (int cc = 0; cc < 4; cc++) {
                float lo, hi;
                UNPK2(lo, hi, acc[p][cc]);
                st[(lb + 2*p)*65 + (ng << 2) + cc]     = lo;
                st[(lb + 2*p + 1)*65 + (ng << 2) + cc] = hi;
            }
        }
        __syncthreads();
        // LayerNorm: 4 threads per row (32 rows), 16 cols each
        int row = tid >> 2, q = tid & 3;
        float v[16], s = 0.f, s2 = 0.f;
#pragma unroll
        for (int j = 0; j < 16; j++) {
            float x = st[row*65 + q*16 + j];
            v[j] = x; s += x; s2 += x * x;
        }
        s  += __shfl_xor_sync(0xffffffffu, s, 1);
        s2 += __shfl_xor_sync(0xffffffffu, s2, 1);
        s  += __shfl_xor_sync(0xffffffffu, s, 2);
        s2 += __shfl_xor_sync(0xffffffffu, s2, 2);
        float mean = s * 0.015625f;
        float var  = s2 * 0.015625f - mean * mean;
        float rstd = rsqrtf(var + 1e-5f);
#pragma unroll
        for (int j = 0; j < 16; j++) {
            int n = q*16 + j;
            st[row*65 + n] = (v[j] - mean) * rstd * __ldg(&lng[n]) + __ldg(&lnb[n]);
        }
        __syncthreads();
        // transposed coalesced write: gout[b][n][lcl + l]
        for (int e = tid; e < 512; e += 128) {
            int n = e >> 3, l4 = e & 7;
            int l = l4 << 2;
            float4 o4 = make_float4(st[l*65 + n],       st[(l+1)*65 + n],
                                    st[(l+2)*65 + n],   st[(l+3)*65 + n]);
            *(float4*)&gout[((long)b*64 + n)*SEQL + lcl + l] = o4;
        }
    }
}

// ---------------- host ----------------
extern "C" void kernel_launch(void* const* d_in, const int* in_sizes, int n_in,
                              void* d_out, int out_size) {
    const float* x1 = (const float*)d_in[0];
    float* out = (float*)d_out;

    float *xr, *hp, *xmid, *w1t, *wxt, *wot, *Ab;
    int* Afl;
    cudaGetSymbolAddress((void**)&xr,   g_xr);
    cudaGetSymbolAddress((void**)&hp,   g_hp);
    cudaGetSymbolAddress((void**)&xmid, g_xmid);
    cudaGetSymbolAddress((void**)&w1t,  g_w1t);
    cudaGetSymbolAddress((void**)&wxt,  g_wxt);
    cudaGetSymbolAddress((void**)&wot,  g_wot);
    cudaGetSymbolAddress((void**)&Ab,   g_Ab);
    cudaGetSymbolAddress((void**)&Afl,  g_Afl);

    prep_k<<<dim3(136, 2), 256>>>(
        (const float*)d_in[1], (const float*)d_in[4], (const float*)d_in[9], (const float*)d_in[7],
        (const float*)d_in[10], (const float*)d_in[13], (const float*)d_in[18], (const float*)d_in[16],
        w1t, wxt, wot, Ab);
    chkA_k<<<2, 256>>>(Ab, Ab + 2048, Afl);

    const int GSM = 33280;
    const int MSM = (2*32*SP + 32*36 + 4480) * 4;   // 56320 B <= 57344 (4 blocks/SM)
    cudaFuncSetAttribute(mega_k, cudaFuncAttributeMaxDynamicSharedMemorySize, MSM);

    for (int m = 0; m < 2; m++) {
        const float* cw  = (const float*)d_in[1 + 9*m + 1];
        const float* cb  = (const float*)d_in[1 + 9*m + 2];
        const float* dtw = (const float*)d_in[1 + 9*m + 4];
        const float* dtb = (const float*)d_in[1 + 9*m + 5];
        const float* Dp  = (const float*)d_in[1 + 9*m + 7];
        const float* lng = (const float*)d_in[19 + 2*m];
        const float* lnb = (const float*)d_in[20 + 2*m];
        const float* Abm = Ab + m*2048;
        const int*   flm = Afl + m;

        const float* Xin = (m == 0) ? x1 : xmid;      // k-major [b][64][4096]
        float* gout = (m == 0) ? xmid : out;          // k-major [b][64][4096]

        // in_proj: K=64, N=256 -> xr row-major [l][256]
        gemm_k<<<dim3(SEQL/64, 4, BATCH), 256, GSM>>>(
            Xin, w1t + m*16384, xr, 64, 256, 256);
        // MEGA: conv + x_proj + scan + out_proj + LN, one persistent launch
        mega_k<<<dim3(NCH, BATCH), DIN, MSM>>>(
            xr, cw, cb, wxt + m*8192, Abm, dtw, dtb, Dp,
            wot + m*8192, lng, lnb, hp, gout, flm);
    }
}